// round 3
// baseline (speedup 1.0000x reference)
#include <cuda_runtime.h>

// Problem constants (fixed shapes)
#define WSZ   64
#define NC    48
#define NT    3
#define NB    4
#define IMG   512
#define KTOT  (NT*NC)            // 144
#define NWIN  (NB*8*8)           // 256
#define WIN_SLAB (KTOT*WSZ*WSZ)  // 589824 floats per window

typedef unsigned long long u64;

// Scratch: G[win][(t*48+c)][H'*64+W']  (576 MiB)
__device__ __align__(16) float g_tmp[(size_t)NWIN * WIN_SLAB];

// Packed dual-fp32 FMA (Blackwell FFMA2): d.lo += a.lo*b.lo ; d.hi += a.hi*b.hi
__device__ __forceinline__ void ffma2(u64& d, u64 a, u64 b) {
    asm("fma.rn.f32x2 %0, %1, %2, %0;" : "+l"(d) : "l"(a), "l"(b));
}
__device__ __forceinline__ float psum(u64 v) {
    float lo, hi;
    asm("mov.b64 {%0, %1}, %2;" : "=f"(lo), "=f"(hi) : "l"(v));
    return lo + hi;
}

// ---------------------------------------------------------------------------
// Kernel A: per (b,c,p,q) window: for each t, tmp1 = X*Ws_t ; tmp2 = Hs_t^T*tmp1
// All contractions run as f32x2 pairs over the k axis (k-pair-interleaved SMEM).
// ---------------------------------------------------------------------------
__global__ __launch_bounds__(256) void k_stage12(
    const float* __restrict__ x,
    const float* __restrict__ Ws,
    const float* __restrict__ Hs)
{
    __shared__ __align__(16) float sX [WSZ*WSZ];    // X[h][w] (w contiguous = k pairs)
    __shared__ __align__(16) float sFI[32*128];     // factor interleaved: [k/2][col*2 + k&1]
    __shared__ __align__(16) float sTp[32*128];     // tmp1 interleaved:   [h/2][W'*2 + h&1]

    const int tid = threadIdx.x;
    const int q = blockIdx.x & 7;
    const int p = blockIdx.x >> 3;
    const int c = blockIdx.y;
    const int b = blockIdx.z;

    // Load 64x64 input window (coalesced float4), plain [h][w] layout
    const float* xw = x + (((size_t)(b*NC + c)*IMG + (size_t)p*WSZ)*IMG + (size_t)q*WSZ);
    #pragma unroll
    for (int i = 0; i < 4; i++) {
        int idx4 = i*256 + tid;
        int h  = idx4 >> 4;
        int w4 = (idx4 & 15) << 2;
        *(float4*)&sX[h*WSZ + w4] = *(const float4*)&xw[(size_t)h*IMG + w4];
    }

    const int ty = tid >> 4, tx = tid & 15;
    const int r0 = ty * 4;          // output rows (h for GEMM1 / H' for GEMM2)
    const int c0 = tx * 4;          // output cols (W')
    float* gwin = g_tmp + (size_t)((b*8 + p)*8 + q) * WIN_SLAB;

    for (int t = 0; t < NT; t++) {
        __syncthreads();   // prev iter's sFI/sTp reads done (sX ready at t=0)

        // --- Load Ws_t k-pair-interleaved: sFI[a][W'*2+par] = Ws[2a+par][W']
        {
            const float* wt = Ws + (size_t)t*WSZ*WSZ;
            #pragma unroll
            for (int i = 0; i < 2; i++) {
                int u = i*256 + tid;            // 0..511 : a = u>>4, col4 = (u&15)*4
                int a = u >> 4;
                int col4 = (u & 15) << 2;
                float4 e = *(const float4*)&wt[(2*a  )*WSZ + col4];
                float4 o = *(const float4*)&wt[(2*a+1)*WSZ + col4];
                float2* dst = (float2*)&sFI[a*128 + col4*2];
                dst[0] = make_float2(e.x, o.x);
                dst[1] = make_float2(e.y, o.y);
                dst[2] = make_float2(e.z, o.z);
                dst[3] = make_float2(e.w, o.w);
            }
        }
        __syncthreads();

        // --- GEMM1: tmp1[h][W'] = sum_w X[h][w] * Ws[w][W'], pairs over w
        {
            u64 acc[4][4];
            #pragma unroll
            for (int i = 0; i < 4; i++)
                #pragma unroll
                for (int j = 0; j < 4; j++) acc[i][j] = 0ULL;

            #pragma unroll 8
            for (int kp = 0; kp < 32; kp++) {
                u64 a0 = *(const u64*)&sX[(r0+0)*WSZ + 2*kp];
                u64 a1 = *(const u64*)&sX[(r0+1)*WSZ + 2*kp];
                u64 a2 = *(const u64*)&sX[(r0+2)*WSZ + 2*kp];
                u64 a3 = *(const u64*)&sX[(r0+3)*WSZ + 2*kp];
                ulonglong2 bP = *(const ulonglong2*)&sFI[kp*128 + c0*2];
                ulonglong2 bQ = *(const ulonglong2*)&sFI[kp*128 + c0*2 + 4];
                ffma2(acc[0][0], a0, bP.x); ffma2(acc[0][1], a0, bP.y);
                ffma2(acc[0][2], a0, bQ.x); ffma2(acc[0][3], a0, bQ.y);
                ffma2(acc[1][0], a1, bP.x); ffma2(acc[1][1], a1, bP.y);
                ffma2(acc[1][2], a1, bQ.x); ffma2(acc[1][3], a1, bQ.y);
                ffma2(acc[2][0], a2, bP.x); ffma2(acc[2][1], a2, bP.y);
                ffma2(acc[2][2], a2, bQ.x); ffma2(acc[2][3], a2, bQ.y);
                ffma2(acc[3][0], a3, bP.x); ffma2(acc[3][1], a3, bP.y);
                ffma2(acc[3][2], a3, bQ.x); ffma2(acc[3][3], a3, bQ.y);
            }

            // Write tmp1 h-pair-interleaved: sTp[h/2][W'*2 + h&1]
            #pragma unroll
            for (int ip = 0; ip < 2; ip++) {
                int hp = 2*ty + ip;     // (r0+2ip)/2
                #pragma unroll
                for (int j = 0; j < 4; j++) {
                    *(float2*)&sTp[hp*128 + (c0+j)*2] =
                        make_float2(psum(acc[2*ip][j]), psum(acc[2*ip+1][j]));
                }
            }
        }
        __syncthreads();

        // --- Load Hs_t k-pair-interleaved into sFI: sFI[a][H'*2+par] = Hs[2a+par][H']
        {
            const float* ht = Hs + (size_t)t*WSZ*WSZ;
            #pragma unroll
            for (int i = 0; i < 2; i++) {
                int u = i*256 + tid;
                int a = u >> 4;
                int col4 = (u & 15) << 2;
                float4 e = *(const float4*)&ht[(2*a  )*WSZ + col4];
                float4 o = *(const float4*)&ht[(2*a+1)*WSZ + col4];
                float2* dst = (float2*)&sFI[a*128 + col4*2];
                dst[0] = make_float2(e.x, o.x);
                dst[1] = make_float2(e.y, o.y);
                dst[2] = make_float2(e.z, o.z);
                dst[3] = make_float2(e.w, o.w);
            }
        }
        __syncthreads();

        // --- GEMM2: tmp2[H'][W'] = sum_h Hs[h][H'] * tmp1[h][W'], pairs over h
        {
            u64 acc[4][4];
            #pragma unroll
            for (int i = 0; i < 4; i++)
                #pragma unroll
                for (int j = 0; j < 4; j++) acc[i][j] = 0ULL;

            #pragma unroll 8
            for (int kp = 0; kp < 32; kp++) {
                ulonglong2 aP = *(const ulonglong2*)&sFI[kp*128 + r0*2];      // H'=r0,r0+1
                ulonglong2 aQ = *(const ulonglong2*)&sFI[kp*128 + r0*2 + 4];  // H'=r0+2,r0+3
                ulonglong2 bP = *(const ulonglong2*)&sTp[kp*128 + c0*2];
                ulonglong2 bQ = *(const ulonglong2*)&sTp[kp*128 + c0*2 + 4];
                ffma2(acc[0][0], aP.x, bP.x); ffma2(acc[0][1], aP.x, bP.y);
                ffma2(acc[0][2], aP.x, bQ.x); ffma2(acc[0][3], aP.x, bQ.y);
                ffma2(acc[1][0], aP.y, bP.x); ffma2(acc[1][1], aP.y, bP.y);
                ffma2(acc[1][2], aP.y, bQ.x); ffma2(acc[1][3], aP.y, bQ.y);
                ffma2(acc[2][0], aQ.x, bP.x); ffma2(acc[2][1], aQ.x, bP.y);
                ffma2(acc[2][2], aQ.x, bQ.x); ffma2(acc[2][3], aQ.x, bQ.y);
                ffma2(acc[3][0], aQ.y, bP.x); ffma2(acc[3][1], aQ.y, bP.y);
                ffma2(acc[3][2], aQ.y, bQ.x); ffma2(acc[3][3], aQ.y, bQ.y);
            }

            float* go = gwin + (size_t)(t*NC + c) * (WSZ*WSZ);
            #pragma unroll
            for (int i = 0; i < 4; i++)
                *(float4*)&go[(r0+i)*WSZ + c0] =
                    make_float4(psum(acc[i][0]), psum(acc[i][1]),
                                psum(acc[i][2]), psum(acc[i][3]));
        }
    }
}

// ---------------------------------------------------------------------------
// Kernel B: per window, out[C'][n] = sum_k Cs[k][C'] * G[win][k][n]
// M=48, K=144, N=4096. Pairs over k via interleaved sCI / sGI.
// ---------------------------------------------------------------------------
__global__ __launch_bounds__(256) void k_stage3(
    const float* __restrict__ Cs,
    float* __restrict__ out)
{
    __shared__ __align__(16) float sCI[72*96];      // [k/2][C'*2 + k&1] : 27648 B
    __shared__ __align__(16) float sGI[8*256];      // [kk/2][n*2 + kk&1]: 8192 B

    const int tid   = threadIdx.x;
    const int win   = blockIdx.y;
    const int ntile = blockIdx.x * 128;

    // Stage Cs k-pair-interleaved: sCI[a][C'*2+par] = Cs[2a+par][C']
    for (int u = tid; u < 864; u += 256) {          // 72 a-rows x 12 col4-groups
        int a  = u / 12;
        int c4 = (u % 12) << 2;
        float4 e = *(const float4*)&Cs[(2*a  )*NC + c4];
        float4 o = *(const float4*)&Cs[(2*a+1)*NC + c4];
        float2* dst = (float2*)&sCI[a*96 + c4*2];
        dst[0] = make_float2(e.x, o.x);
        dst[1] = make_float2(e.y, o.y);
        dst[2] = make_float2(e.z, o.z);
        dst[3] = make_float2(e.w, o.w);
    }

    const float* gw = g_tmp + (size_t)win * WIN_SLAB + ntile;
    const int mg = tid >> 5;          // 0..7 (uniform per warp -> sCI reads broadcast)
    const int ng = tid & 31;
    const int C0 = mg * 6;
    const int n0 = ng * 4;

    u64 acc[6][4];
    #pragma unroll
    for (int i = 0; i < 6; i++)
        #pragma unroll
        for (int j = 0; j < 4; j++) acc[i][j] = 0ULL;

    const int ga = tid >> 5;          // sGI stage: row-pair index 0..7
    const int gc = (tid & 31) << 2;   // col4

    for (int k0 = 0; k0 < KTOT; k0 += 16) {
        __syncthreads();   // prev chunk's sGI reads done (covers sCI at k0=0)

        // Load 16 G rows k-pair-interleaved: one (a, col4) unit per thread
        {
            const float* g0 = gw + (size_t)(k0 + 2*ga) * (WSZ*WSZ) + gc;
            float4 e = *(const float4*)g0;
            float4 o = *(const float4*)(g0 + WSZ*WSZ);
            float2* dst = (float2*)&sGI[ga*256 + gc*2];
            dst[0] = make_float2(e.x, o.x);
            dst[1] = make_float2(e.y, o.y);
            dst[2] = make_float2(e.z, o.z);
            dst[3] = make_float2(e.w, o.w);
        }
        __syncthreads();

        const int arow0 = k0 >> 1;
        #pragma unroll
        for (int kk = 0; kk < 8; kk++) {
            ulonglong2 aA = *(const ulonglong2*)&sCI[(arow0+kk)*96 + C0*2];      // C0,C0+1
            ulonglong2 aB = *(const ulonglong2*)&sCI[(arow0+kk)*96 + C0*2 + 4];  // C0+2,C0+3
            ulonglong2 aC = *(const ulonglong2*)&sCI[(arow0+kk)*96 + C0*2 + 8];  // C0+4,C0+5
            ulonglong2 bP = *(const ulonglong2*)&sGI[kk*256 + n0*2];
            ulonglong2 bQ = *(const ulonglong2*)&sGI[kk*256 + n0*2 + 4];
            ffma2(acc[0][0], aA.x, bP.x); ffma2(acc[0][1], aA.x, bP.y);
            ffma2(acc[0][2], aA.x, bQ.x); ffma2(acc[0][3], aA.x, bQ.y);
            ffma2(acc[1][0], aA.y, bP.x); ffma2(acc[1][1], aA.y, bP.y);
            ffma2(acc[1][2], aA.y, bQ.x); ffma2(acc[1][3], aA.y, bQ.y);
            ffma2(acc[2][0], aB.x, bP.x); ffma2(acc[2][1], aB.x, bP.y);
            ffma2(acc[2][2], aB.x, bQ.x); ffma2(acc[2][3], aB.x, bQ.y);
            ffma2(acc[3][0], aB.y, bP.x); ffma2(acc[3][1], aB.y, bP.y);
            ffma2(acc[3][2], aB.y, bQ.x); ffma2(acc[3][3], aB.y, bQ.y);
            ffma2(acc[4][0], aC.x, bP.x); ffma2(acc[4][1], aC.x, bP.y);
            ffma2(acc[4][2], aC.x, bQ.x); ffma2(acc[4][3], aC.x, bQ.y);
            ffma2(acc[5][0], aC.y, bP.x); ffma2(acc[5][1], aC.y, bP.y);
            ffma2(acc[5][2], aC.y, bQ.x); ffma2(acc[5][3], aC.y, bQ.y);
        }
    }

    // Scatter to output: out[b][C'][p*64+H'][q*64+W']
    const int b = win >> 6;
    const int p = (win >> 3) & 7;
    const int q = win & 7;
    const int n  = ntile + n0;
    const int Hp = n >> 6;
    const int Wp = n & 63;
    #pragma unroll
    for (int i = 0; i < 6; i++) {
        int Cp = C0 + i;
        float* op = out + ((((size_t)b*NC + Cp)*IMG + (size_t)p*WSZ + Hp)*IMG
                           + (size_t)q*WSZ + Wp);
        *(float4*)op = make_float4(psum(acc[i][0]), psum(acc[i][1]),
                                   psum(acc[i][2]), psum(acc[i][3]));
    }
}

extern "C" void kernel_launch(void* const* d_in, const int* in_sizes, int n_in,
                              void* d_out, int out_size)
{
    const float* x  = (const float*)d_in[0];
    const float* Ws = (const float*)d_in[1];
    const float* Hs = (const float*)d_in[2];
    const float* Cs = (const float*)d_in[3];
    float* out = (float*)d_out;

    dim3 gA(64, NC, NB);
    k_stage12<<<gA, 256>>>(x, Ws, Hs);

    dim3 gB(WSZ*WSZ/128, NWIN);
    k_stage3<<<gB, 256>>>(Cs, out);
}

// round 4
// speedup vs baseline: 1.8368x; 1.8368x over previous
#include <cuda_runtime.h>
#include <cuda_bf16.h>
#include <cstdint>

// Problem constants (fixed shapes)
#define WSZ   64
#define NC    48
#define NT    3
#define NB    4
#define IMG   512
#define KTOT  (NT*NC)            // 144
#define NWIN  (NB*8*8)           // 256
#define WIN_SLAB (KTOT*WSZ*WSZ)  // 589824 floats per window

// Scratch: G[win][(t*48+c)][H'*64+W']  (576 MiB)
__device__ __align__(16) float g_tmp[(size_t)NWIN * WIN_SLAB];

#define LDPAD 72   // row stride (bf16 elems): 144B = 9*16B (aligned, 4-bank row shift)

// ---------------------------------------------------------------------------
// helpers
// ---------------------------------------------------------------------------
__device__ __forceinline__ uint32_t smem_u32(const void* p) {
    uint32_t a;
    asm("{ .reg .u64 t; cvta.to.shared.u64 t, %1; cvt.u32.u64 %0, t; }"
        : "=r"(a) : "l"(p));
    return a;
}

__device__ __forceinline__ void bsplit(float x, unsigned short& h, unsigned short& l) {
    __nv_bfloat16 bh = __float2bfloat16(x);
    float r = x - __bfloat162float(bh);
    __nv_bfloat16 bl = __float2bfloat16(r);
    h = *reinterpret_cast<unsigned short*>(&bh);
    l = *reinterpret_cast<unsigned short*>(&bl);
}

__device__ __forceinline__ void ldsm4(uint32_t* r, uint32_t addr) {
    asm volatile("ldmatrix.sync.aligned.m8n8.x4.shared.b16 {%0,%1,%2,%3}, [%4];"
                 : "=r"(r[0]), "=r"(r[1]), "=r"(r[2]), "=r"(r[3]) : "r"(addr));
}
__device__ __forceinline__ void ldsm2(uint32_t& r0, uint32_t& r1, uint32_t addr) {
    asm volatile("ldmatrix.sync.aligned.m8n8.x2.shared.b16 {%0,%1}, [%2];"
                 : "=r"(r0), "=r"(r1) : "r"(addr));
}
__device__ __forceinline__ void mma16816(float* d, const uint32_t* a,
                                         uint32_t b0, uint32_t b1) {
    asm volatile(
        "mma.sync.aligned.m16n8k16.row.col.f32.bf16.bf16.f32 "
        "{%0,%1,%2,%3},{%4,%5,%6,%7},{%8,%9},{%0,%1,%2,%3};"
        : "+f"(d[0]), "+f"(d[1]), "+f"(d[2]), "+f"(d[3])
        : "r"(a[0]), "r"(a[1]), "r"(a[2]), "r"(a[3]), "r"(b0), "r"(b1));
}

// 64x64x64 GEMM, bf16x3 (Ah*Bh + Ah*Bl + Al*Bh), acc fp32.
// A[m][k] in (aAh,aAl) row-major stride LDPAD; B[k][n] stored as [n][k] in
// (aBh,aBl). Warp computes 16(m) x 32(n) tile at (mrow, ncol0).
// Frag layouts per PTX mma.m16n8k16.
__device__ __forceinline__ void gemm64(
    uint32_t aAh, uint32_t aAl, uint32_t aBh, uint32_t aBl,
    int mrow, int ncol0, int lane, float acc[4][4])
{
    // ldmatrix lane address components
    const int rA = (lane & 7) + ((lane >> 3) & 1) * 8;
    const int cA = ((lane >> 4) & 1) * 8;
    const uint32_t pA = (uint32_t)(((mrow + rA) * LDPAD + cA) * 2);
    const int rB = lane & 7;
    const int cB = ((lane >> 3) & 1) * 8;
    const uint32_t pB = (uint32_t)((rB * LDPAD + cB) * 2);

    #pragma unroll
    for (int ks = 0; ks < 4; ks++) {
        const int k0 = ks * 16;
        uint32_t ah[4], al[4];
        ldsm4(ah, aAh + pA + k0 * 2);
        ldsm4(al, aAl + pA + k0 * 2);
        #pragma unroll
        for (int i = 0; i < 4; i++) {
            const uint32_t boff = (uint32_t)(((ncol0 + 8 * i) * LDPAD + k0) * 2) + pB;
            uint32_t bh0, bh1, bl0, bl1;
            ldsm2(bh0, bh1, aBh + boff);
            ldsm2(bl0, bl1, aBl + boff);
            mma16816(acc[i], ah, bh0, bh1);
            mma16816(acc[i], ah, bl0, bl1);
            mma16816(acc[i], al, bh0, bh1);
        }
    }
}

// ---------------------------------------------------------------------------
// Kernel A (tensor): per (b,c,p,q) window, for each t:
//   GEMM1': tmp1^T[W'][h] = sum_w Ws_t[w][W'] * X[h][w]   (A=F=Ws^T, B=XT=X)
//   GEMM2 : tmp2[H'][W']  = sum_h Hs_t[h][H'] * tmp1[h][W'] (A=F=Hs^T, B=XT=tmp1^T)
// XT array is reused for X then tmp1^T (X reloaded per t from L1/L2).
// ---------------------------------------------------------------------------
__global__ __launch_bounds__(256) void k_stage12(
    const float* __restrict__ x,
    const float* __restrict__ Ws,
    const float* __restrict__ Hs)
{
    __shared__ __align__(16) unsigned short sXTh[WSZ * LDPAD];
    __shared__ __align__(16) unsigned short sXTl[WSZ * LDPAD];
    __shared__ __align__(16) unsigned short sFh [WSZ * LDPAD];
    __shared__ __align__(16) unsigned short sFl [WSZ * LDPAD];

    const int tid  = threadIdx.x;
    const int lane = tid & 31;
    const int wid  = tid >> 5;
    const int mrow  = (wid & 3) * 16;
    const int ncol0 = (wid >> 2) * 32;

    const int q = blockIdx.x & 7;
    const int p = blockIdx.x >> 3;
    const int c = blockIdx.y;
    const int b = blockIdx.z;

    const uint32_t aXh = smem_u32(sXTh), aXl = smem_u32(sXTl);
    const uint32_t aFh = smem_u32(sFh),  aFl = smem_u32(sFl);

    const float* xw = x + (((size_t)(b*NC + c)*IMG + (size_t)p*WSZ)*IMG + (size_t)q*WSZ);
    float* gwin = g_tmp + (size_t)((b*8 + p)*8 + q) * WIN_SLAB;

    // epilogue lane coords
    const int erow = lane >> 2;          // 0..7
    const int ecol = (lane & 3) * 2;     // 0,2,4,6

    for (int t = 0; t < NT; t++) {
        __syncthreads();   // prev t's GEMM2 reads of F/XT done

        // Load X -> XT (natural [h][w]) and Ws_t -> F transposed ([W'][w])
        #pragma unroll
        for (int it = 0; it < 16; it++) {
            int u = it * 256 + tid;
            int r = u >> 6, cc = u & 63;
            bsplit(xw[(size_t)r * IMG + cc], sXTh[r*LDPAD + cc], sXTl[r*LDPAD + cc]);
        }
        {
            const float* wt = Ws + (size_t)t * WSZ * WSZ;
            #pragma unroll
            for (int it = 0; it < 16; it++) {
                int u = it * 256 + tid;
                int w = u >> 6, Wp = u & 63;
                bsplit(wt[u], sFh[Wp*LDPAD + w], sFl[Wp*LDPAD + w]);
            }
        }
        __syncthreads();

        // GEMM1': acc = tmp1^T tile (rows W' = mrow.., cols h = ncol0..)
        float acc[4][4];
        #pragma unroll
        for (int i = 0; i < 4; i++)
            #pragma unroll
            for (int j = 0; j < 4; j++) acc[i][j] = 0.0f;
        gemm64(aFh, aFl, aXh, aXl, mrow, ncol0, lane, acc);

        __syncthreads();   // all warps done reading XT(X) and F(Ws)

        // Epilogue1: write tmp1^T into XT (bf16 hi/lo), rows=W', cols=h.
        #pragma unroll
        for (int i = 0; i < 4; i++) {
            int colh = ncol0 + 8*i + ecol;
            int rw0 = mrow + erow, rw1 = rw0 + 8;
            unsigned short h0, l0, h1, l1;
            bsplit(acc[i][0], h0, l0); bsplit(acc[i][1], h1, l1);
            *(uint32_t*)&sXTh[rw0*LDPAD + colh] = (uint32_t)h0 | ((uint32_t)h1 << 16);
            *(uint32_t*)&sXTl[rw0*LDPAD + colh] = (uint32_t)l0 | ((uint32_t)l1 << 16);
            bsplit(acc[i][2], h0, l0); bsplit(acc[i][3], h1, l1);
            *(uint32_t*)&sXTh[rw1*LDPAD + colh] = (uint32_t)h0 | ((uint32_t)h1 << 16);
            *(uint32_t*)&sXTl[rw1*LDPAD + colh] = (uint32_t)l0 | ((uint32_t)l1 << 16);
        }
        // Load Hs_t -> F transposed ([H'][h])
        {
            const float* ht = Hs + (size_t)t * WSZ * WSZ;
            #pragma unroll
            for (int it = 0; it < 16; it++) {
                int u = it * 256 + tid;
                int h = u >> 6, Hp = u & 63;
                bsplit(ht[u], sFh[Hp*LDPAD + h], sFl[Hp*LDPAD + h]);
            }
        }
        __syncthreads();

        // GEMM2: acc = tmp2 tile (rows H' = mrow.., cols W' = ncol0..)
        #pragma unroll
        for (int i = 0; i < 4; i++)
            #pragma unroll
            for (int j = 0; j < 4; j++) acc[i][j] = 0.0f;
        gemm64(aFh, aFl, aXh, aXl, mrow, ncol0, lane, acc);

        // Write tmp2 to g_tmp (fp32)
        float* go = gwin + (size_t)(t*NC + c) * (WSZ*WSZ);
        #pragma unroll
        for (int i = 0; i < 4; i++) {
            int colw = ncol0 + 8*i + ecol;
            int rw0 = mrow + erow, rw1 = rw0 + 8;
            *(float2*)&go[rw0*WSZ + colw] = make_float2(acc[i][0], acc[i][1]);
            *(float2*)&go[rw1*WSZ + colw] = make_float2(acc[i][2], acc[i][3]);
        }
    }
}

// ---------------------------------------------------------------------------
// Kernel B (unchanged from R2): per window, out[C'][n] = sum_k Cs[k][C'] G[k][n]
// ---------------------------------------------------------------------------
__global__ __launch_bounds__(256) void k_stage3(
    const float* __restrict__ Cs,
    float* __restrict__ out)
{
    __shared__ __align__(16) float sC[KTOT*NC];     // 144*48
    __shared__ __align__(16) float sG[16*128];

    const int tid   = threadIdx.x;
    const int win   = blockIdx.y;
    const int ntile = blockIdx.x * 128;

    {
        const float4* src = (const float4*)Cs;
        float4* dst = (float4*)sC;
        for (int i = tid; i < (KTOT*NC)/4; i += 256) dst[i] = src[i];
    }

    const float* gw = g_tmp + (size_t)win * WIN_SLAB + ntile;
    const int mg = tid >> 5;
    const int ng = tid & 31;
    const int C0 = mg * 6;
    const int n0 = ng * 4;

    float acc[6][4];
    #pragma unroll
    for (int i = 0; i < 6; i++)
        #pragma unroll
        for (int j = 0; j < 4; j++) acc[i][j] = 0.0f;

    for (int k0 = 0; k0 < KTOT; k0 += 16) {
        __syncthreads();
        #pragma unroll
        for (int i = 0; i < 2; i++) {
            int idx4 = i*256 + tid;
            int kk = idx4 >> 5;
            int j4 = (idx4 & 31) << 2;
            *(float4*)&sG[kk*128 + j4] =
                *(const float4*)&gw[(size_t)(k0 + kk)*(WSZ*WSZ) + j4];
        }
        __syncthreads();

        #pragma unroll
        for (int kk = 0; kk < 16; kk++) {
            float4 gv = *(const float4*)&sG[kk*128 + n0];
            const float* cr = &sC[(k0 + kk)*NC + C0];
            float cv0 = cr[0], cv1 = cr[1], cv2 = cr[2];
            float cv3 = cr[3], cv4 = cr[4], cv5 = cr[5];
            acc[0][0] += cv0*gv.x; acc[0][1] += cv0*gv.y; acc[0][2] += cv0*gv.z; acc[0][3] += cv0*gv.w;
            acc[1][0] += cv1*gv.x; acc[1][1] += cv1*gv.y; acc[1][2] += cv1*gv.z; acc[1][3] += cv1*gv.w;
            acc[2][0] += cv2*gv.x; acc[2][1] += cv2*gv.y; acc[2][2] += cv2*gv.z; acc[2][3] += cv2*gv.w;
            acc[3][0] += cv3*gv.x; acc[3][1] += cv3*gv.y; acc[3][2] += cv3*gv.z; acc[3][3] += cv3*gv.w;
            acc[4][0] += cv4*gv.x; acc[4][1] += cv4*gv.y; acc[4][2] += cv4*gv.z; acc[4][3] += cv4*gv.w;
            acc[5][0] += cv5*gv.x; acc[5][1] += cv5*gv.y; acc[5][2] += cv5*gv.z; acc[5][3] += cv5*gv.w;
        }
    }

    const int b = win >> 6;
    const int p = (win >> 3) & 7;
    const int q = win & 7;
    const int n  = ntile + n0;
    const int Hp = n >> 6;
    const int Wp = n & 63;
    #pragma unroll
    for (int i = 0; i < 6; i++) {
        int Cp = C0 + i;
        float* op = out + ((((size_t)b*NC + Cp)*IMG + (size_t)p*WSZ + Hp)*IMG
                           + (size_t)q*WSZ + Wp);
        *(float4*)op = make_float4(acc[i][0], acc[i][1], acc[i][2], acc[i][3]);
    }
}

extern "C" void kernel_launch(void* const* d_in, const int* in_sizes, int n_in,
                              void* d_out, int out_size)
{
    const float* x  = (const float*)d_in[0];
    const float* Ws = (const float*)d_in[1];
    const float* Hs = (const float*)d_in[2];
    const float* Cs = (const float*)d_in[3];
    float* out = (float*)d_out;

    dim3 gA(64, NC, NB);
    k_stage12<<<gA, 256>>>(x, Ws, Hs);

    dim3 gB(WSZ*WSZ/128, NWIN);
    k_stage3<<<gB, 256>>>(Cs, out);
}

// round 6
// speedup vs baseline: 2.6877x; 1.4633x over previous
#include <cuda_runtime.h>
#include <cuda_bf16.h>
#include <cstdint>

// Problem constants
#define WSZ   64
#define NC    48
#define NT    3
#define NB    4
#define IMG   512
#define KTOT  (NT*NC)            // 144
#define NWIN  (NB*8*8)           // 256
#define WIN_SLAB (KTOT*WSZ*WSZ)  // 589824 floats per window

// Scratch: G[win][(t*48+c)][H'][W']  (576 MiB)
__device__ __align__(16) float g_tmp[(size_t)NWIN * WIN_SLAB];

// Pre-split, pre-transposed factors (bf16 hi/lo), [t][n][k] (n=W'/H', k=w/h)
__device__ __align__(16) unsigned short FWh[NT*WSZ*WSZ], FWl[NT*WSZ*WSZ];
__device__ __align__(16) unsigned short FHh[NT*WSZ*WSZ], FHl[NT*WSZ*WSZ];

// ---------------------------------------------------------------------------
// helpers
// ---------------------------------------------------------------------------
__device__ __forceinline__ uint32_t smem_u32(const void* p) {
    uint32_t a;
    asm("{ .reg .u64 t; cvta.to.shared.u64 t, %1; cvt.u32.u64 %0, t; }"
        : "=r"(a) : "l"(p));
    return a;
}
__device__ __forceinline__ void bsplit(float x, unsigned short& h, unsigned short& l) {
    __nv_bfloat16 bh = __float2bfloat16(x);
    float r = x - __bfloat162float(bh);
    __nv_bfloat16 bl = __float2bfloat16(r);
    h = *reinterpret_cast<unsigned short*>(&bh);
    l = *reinterpret_cast<unsigned short*>(&bl);
}
__device__ __forceinline__ void ldsm4(uint32_t* r, uint32_t addr) {
    asm volatile("ldmatrix.sync.aligned.m8n8.x4.shared.b16 {%0,%1,%2,%3}, [%4];"
                 : "=r"(r[0]), "=r"(r[1]), "=r"(r[2]), "=r"(r[3]) : "r"(addr));
}
__device__ __forceinline__ void mma16816(float* d, const uint32_t* a,
                                         uint32_t b0, uint32_t b1) {
    asm volatile(
        "mma.sync.aligned.m16n8k16.row.col.f32.bf16.bf16.f32 "
        "{%0,%1,%2,%3},{%4,%5,%6,%7},{%8,%9},{%0,%1,%2,%3};"
        : "+f"(d[0]), "+f"(d[1]), "+f"(d[2]), "+f"(d[3])
        : "r"(a[0]), "r"(a[1]), "r"(a[2]), "r"(a[3]), "r"(b0), "r"(b1));
}

// SMEM byte stride per 64-elem bf16 row (8-short pad)
#define RSTRIDE 144

// 64x64x64 bf16x3 GEMM, warp tile 32(m) x 32(n). A row-major [m][k], B [n][k],
// both bf16 hi/lo at byte-stride RSTRIDE. acc[mt][g][4]: mt = m16 tile, g = n8 group.
__device__ __forceinline__ void gemm64_32(
    uint32_t aAh, uint32_t aAl, uint32_t aBh, uint32_t aBl,
    int mrow, int ncol0, int lane, float acc[2][4][4])
{
    const int rA = lane & 15;
    const int cA = (lane >> 4) * 8;
    const int mB = lane >> 3;
    const int nB = (mB >> 1) * 8 + (lane & 7);
    const int kB = (mB & 1) * 8;
    const uint32_t pA0 = (uint32_t)((mrow + rA) * RSTRIDE + cA * 2);
    const uint32_t pA1 = pA0 + 16 * RSTRIDE;
    const uint32_t pB0 = (uint32_t)((ncol0 + nB) * RSTRIDE + kB * 2);
    const uint32_t pB1 = pB0 + 16 * RSTRIDE;

    #pragma unroll
    for (int ks = 0; ks < 4; ks++) {
        const uint32_t ko = ks * 32;   // 16 bf16 = 32 bytes along k
        uint32_t ah0[4], ah1[4], al0[4], al1[4];
        ldsm4(ah0, aAh + pA0 + ko);
        ldsm4(ah1, aAh + pA1 + ko);
        ldsm4(al0, aAl + pA0 + ko);
        ldsm4(al1, aAl + pA1 + ko);
        uint32_t bh0[4], bh1[4], bl0[4], bl1[4];
        ldsm4(bh0, aBh + pB0 + ko);    // ngroups 0,1 (b0,b1 each)
        ldsm4(bh1, aBh + pB1 + ko);    // ngroups 2,3
        ldsm4(bl0, aBl + pB0 + ko);
        ldsm4(bl1, aBl + pB1 + ko);

        // Ah*Bh
        mma16816(acc[0][0], ah0, bh0[0], bh0[1]);
        mma16816(acc[0][1], ah0, bh0[2], bh0[3]);
        mma16816(acc[0][2], ah0, bh1[0], bh1[1]);
        mma16816(acc[0][3], ah0, bh1[2], bh1[3]);
        mma16816(acc[1][0], ah1, bh0[0], bh0[1]);
        mma16816(acc[1][1], ah1, bh0[2], bh0[3]);
        mma16816(acc[1][2], ah1, bh1[0], bh1[1]);
        mma16816(acc[1][3], ah1, bh1[2], bh1[3]);
        // Ah*Bl
        mma16816(acc[0][0], ah0, bl0[0], bl0[1]);
        mma16816(acc[0][1], ah0, bl0[2], bl0[3]);
        mma16816(acc[0][2], ah0, bl1[0], bl1[1]);
        mma16816(acc[0][3], ah0, bl1[2], bl1[3]);
        mma16816(acc[1][0], ah1, bl0[0], bl0[1]);
        mma16816(acc[1][1], ah1, bl0[2], bl0[3]);
        mma16816(acc[1][2], ah1, bl1[0], bl1[1]);
        mma16816(acc[1][3], ah1, bl1[2], bl1[3]);
        // Al*Bh
        mma16816(acc[0][0], al0, bh0[0], bh0[1]);
        mma16816(acc[0][1], al0, bh0[2], bh0[3]);
        mma16816(acc[0][2], al0, bh1[0], bh1[1]);
        mma16816(acc[0][3], al0, bh1[2], bh1[3]);
        mma16816(acc[1][0], al1, bh0[0], bh0[1]);
        mma16816(acc[1][1], al1, bh0[2], bh0[3]);
        mma16816(acc[1][2], al1, bh1[0], bh1[1]);
        mma16816(acc[1][3], al1, bh1[2], bh1[3]);
    }
}

// ---------------------------------------------------------------------------
// Prep: transpose + bf16-split factor matrices into global (runs once, tiny)
// ---------------------------------------------------------------------------
__global__ void k_prep(const float* __restrict__ Ws, const float* __restrict__ Hs)
{
    int u = blockIdx.x * 256 + threadIdx.x;           // 0..12287
    if (u >= NT*WSZ*WSZ) return;
    int t = u >> 12;
    int r = u & 4095;
    int k = r >> 6;       // source row (w / h)
    int n = r & 63;       // source col (W' / H')
    unsigned short h, l;
    bsplit(Ws[u], h, l);
    FWh[(t << 12) + n*WSZ + k] = h;
    FWl[(t << 12) + n*WSZ + k] = l;
    bsplit(Hs[u], h, l);
    FHh[(t << 12) + n*WSZ + k] = h;
    FHl[(t << 12) + n*WSZ + k] = l;
}

// SMEM layout (bytes): 6 buffers of 64 rows x RSTRIDE
#define OXH 0
#define OXL 9216
#define OTH 18432
#define OTL 27648
#define OFH 36864
#define OFL 46080
#define SM_TOTAL 55296

// ---------------------------------------------------------------------------
// Stage12: CTA = (b, c, window). X staged+split once; per t:
//   GEMM1: tmp1^T[W'][h] = Ws^T[W'][w] . X[h][w]      (A=F, B=X)
//   GEMM2: tmp2 [H'][W'] = Hs^T[H'][h] . tmp1^T[W'][h] (A=F, B=T1)
// ---------------------------------------------------------------------------
__global__ void __launch_bounds__(128) k_stage12(const float* __restrict__ x)
{
    extern __shared__ __align__(16) char smem[];
    const uint32_t S = smem_u32(smem);
    const uint32_t XH = S+OXH, XL = S+OXL, TH = S+OTH, TL = S+OTL,
                   FH = S+OFH, FL = S+OFL;

    const int tid  = threadIdx.x;
    const int lane = tid & 31;
    const int wid  = tid >> 5;
    const int mrow  = (wid >> 1) * 32;
    const int ncol0 = (wid & 1) * 32;

    const int win = blockIdx.x, c = blockIdx.y, b = blockIdx.z;
    const int q = win & 7, p = win >> 3;

    // --- Stage X (bf16 hi/lo split) once: [h][w], stride RSTRIDE
    const float* xw = x + (((size_t)(b*NC + c)*IMG + (size_t)p*WSZ)*IMG + (size_t)q*WSZ);
    #pragma unroll
    for (int it = 0; it < 8; it++) {
        int u = it*128 + tid;          // float4 idx 0..1023
        int r = u >> 4, w4 = (u & 15) << 2;
        float4 v = *(const float4*)&xw[(size_t)r*IMG + w4];
        unsigned short h0,l0,h1,l1,h2,l2,h3,l3;
        bsplit(v.x,h0,l0); bsplit(v.y,h1,l1); bsplit(v.z,h2,l2); bsplit(v.w,h3,l3);
        uint32_t off = (uint32_t)(r*RSTRIDE + w4*2);
        *(uint32_t*)(smem + OXH + off)     = (uint32_t)h0 | ((uint32_t)h1 << 16);
        *(uint32_t*)(smem + OXH + off + 4) = (uint32_t)h2 | ((uint32_t)h3 << 16);
        *(uint32_t*)(smem + OXL + off)     = (uint32_t)l0 | ((uint32_t)l1 << 16);
        *(uint32_t*)(smem + OXL + off + 4) = (uint32_t)l2 | ((uint32_t)l3 << 16);
    }

    float* gwin = g_tmp + (size_t)((b*8 + p)*8 + q) * WIN_SLAB;
    const int erow = lane >> 2;
    const int ecol = (lane & 3) * 2;

    for (int t = 0; t < NT; t++) {
        __syncthreads();   // prev t's F/T1 reads complete

        // Copy Ws_t^T (pre-split) -> F (pure uint4 copies)
        {
            const uint4* sh = (const uint4*)(FWh + (t << 12));
            const uint4* sl = (const uint4*)(FWl + (t << 12));
            #pragma unroll
            for (int i = 0; i < 4; i++) {
                int idx = i*128 + tid;               // 0..511 (8 uint4 per row)
                uint32_t off = (uint32_t)((idx >> 3)*RSTRIDE + (idx & 7)*16);
                *(uint4*)(smem + OFH + off) = sh[idx];
                *(uint4*)(smem + OFL + off) = sl[idx];
            }
        }
        __syncthreads();   // F ready (and X ready at t=0)

        float acc[2][4][4];
        #pragma unroll
        for (int a1 = 0; a1 < 2; a1++)
            #pragma unroll
            for (int a2 = 0; a2 < 4; a2++)
                #pragma unroll
                for (int a3 = 0; a3 < 4; a3++) acc[a1][a2][a3] = 0.0f;
        gemm64_32(FH, FL, XH, XL, mrow, ncol0, lane, acc);
        __syncthreads();   // all F(Ws)/X reads done before F overwrite

        // Epilogue1: split acc -> T1 [W'][h] (rows=W'=mrow.., cols=h=ncol0..)
        #pragma unroll
        for (int mt = 0; mt < 2; mt++)
            #pragma unroll
            for (int g = 0; g < 4; g++) {
                int row = mrow + mt*16 + erow;
                int hc  = ncol0 + g*8 + ecol;
                unsigned short hA,lA,hB,lB;
                bsplit(acc[mt][g][0], hA, lA); bsplit(acc[mt][g][1], hB, lB);
                uint32_t o0 = (uint32_t)(row*RSTRIDE + hc*2);
                *(uint32_t*)(smem + OTH + o0) = (uint32_t)hA | ((uint32_t)hB << 16);
                *(uint32_t*)(smem + OTL + o0) = (uint32_t)lA | ((uint32_t)lB << 16);
                bsplit(acc[mt][g][2], hA, lA); bsplit(acc[mt][g][3], hB, lB);
                uint32_t o1 = o0 + 8*RSTRIDE;
                *(uint32_t*)(smem + OTH + o1) = (uint32_t)hA | ((uint32_t)hB << 16);
                *(uint32_t*)(smem + OTL + o1) = (uint32_t)lA | ((uint32_t)lB << 16);
            }

        // Copy Hs_t^T -> F (concurrent with T1 writes; disjoint regions)
        {
            const uint4* sh = (const uint4*)(FHh + (t << 12));
            const uint4* sl = (const uint4*)(FHl + (t << 12));
            #pragma unroll
            for (int i = 0; i < 4; i++) {
                int idx = i*128 + tid;
                uint32_t off = (uint32_t)((idx >> 3)*RSTRIDE + (idx & 7)*16);
                *(uint4*)(smem + OFH + off) = sh[idx];
                *(uint4*)(smem + OFL + off) = sl[idx];
            }
        }
        __syncthreads();   // T1 + F(Hs) ready

        #pragma unroll
        for (int a1 = 0; a1 < 2; a1++)
            #pragma unroll
            for (int a2 = 0; a2 < 4; a2++)
                #pragma unroll
                for (int a3 = 0; a3 < 4; a3++) acc[a1][a2][a3] = 0.0f;
        gemm64_32(FH, FL, TH, TL, mrow, ncol0, lane, acc);

        // Epilogue2: acc rows=H', cols=W' -> G[(t,c)][H'][W'] (float2 STG)
        float* go = gwin + (size_t)(t*NC + c) * (WSZ*WSZ);
        #pragma unroll
        for (int mt = 0; mt < 2; mt++)
            #pragma unroll
            for (int g = 0; g < 4; g++) {
                int Hp = mrow + mt*16 + erow;
                int Wp = ncol0 + g*8 + ecol;
                *(float2*)&go[Hp*WSZ + Wp]     = make_float2(acc[mt][g][0], acc[mt][g][1]);
                *(float2*)&go[(Hp+8)*WSZ + Wp] = make_float2(acc[mt][g][2], acc[mt][g][3]);
            }
    }
}

// ---------------------------------------------------------------------------
// Stage3 (unchanged R2): out[C'][n] = sum_k Cs[k][C'] * G[win][k][n]
// ---------------------------------------------------------------------------
__global__ __launch_bounds__(256) void k_stage3(
    const float* __restrict__ Cs,
    float* __restrict__ out)
{
    __shared__ __align__(16) float sC[KTOT*NC];
    __shared__ __align__(16) float sG[16*128];

    const int tid   = threadIdx.x;
    const int win   = blockIdx.y;
    const int ntile = blockIdx.x * 128;

    {
        const float4* src = (const float4*)Cs;
        float4* dst = (float4*)sC;
        for (int i = tid; i < (KTOT*NC)/4; i += 256) dst[i] = src[i];
    }

    const float* gw = g_tmp + (size_t)win * WIN_SLAB + ntile;
    const int mg = tid >> 5;
    const int ng = tid & 31;
    const int C0 = mg * 6;
    const int n0 = ng * 4;

    float acc[6][4];
    #pragma unroll
    for (int i = 0; i < 6; i++)
        #pragma unroll
        for (int j = 0; j < 4; j++) acc[i][j] = 0.0f;

    for (int k0 = 0; k0 < KTOT; k0 += 16) {
        __syncthreads();
        #pragma unroll
        for (int i = 0; i < 2; i++) {
            int idx4 = i*256 + tid;
            int kk = idx4 >> 5;
            int j4 = (idx4 & 31) << 2;
            *(float4*)&sG[kk*128 + j4] =
                *(const float4*)&gw[(size_t)(k0 + kk)*(WSZ*WSZ) + j4];
        }
        __syncthreads();

        #pragma unroll
        for (int kk = 0; kk < 16; kk++) {
            float4 gv = *(const float4*)&sG[kk*128 + n0];
            const float* cr = &sC[(k0 + kk)*NC + C0];
            float cv0 = cr[0], cv1 = cr[1], cv2 = cr[2];
            float cv3 = cr[3], cv4 = cr[4], cv5 = cr[5];
            acc[0][0] += cv0*gv.x; acc[0][1] += cv0*gv.y; acc[0][2] += cv0*gv.z; acc[0][3] += cv0*gv.w;
            acc[1][0] += cv1*gv.x; acc[1][1] += cv1*gv.y; acc[1][2] += cv1*gv.z; acc[1][3] += cv1*gv.w;
            acc[2][0] += cv2*gv.x; acc[2][1] += cv2*gv.y; acc[2][2] += cv2*gv.z; acc[2][3] += cv2*gv.w;
            acc[3][0] += cv3*gv.x; acc[3][1] += cv3*gv.y; acc[3][2] += cv3*gv.z; acc[3][3] += cv3*gv.w;
            acc[4][0] += cv4*gv.x; acc[4][1] += cv4*gv.y; acc[4][2] += cv4*gv.z; acc[4][3] += cv4*gv.w;
            acc[5][0] += cv5*gv.x; acc[5][1] += cv5*gv.y; acc[5][2] += cv5*gv.z; acc[5][3] += cv5*gv.w;
        }
    }

    const int b = win >> 6;
    const int p = (win >> 3) & 7;
    const int q = win & 7;
    const int n  = ntile + n0;
    const int Hp = n >> 6;
    const int Wp = n & 63;
    #pragma unroll
    for (int i = 0; i < 6; i++) {
        int Cp = C0 + i;
        float* op = out + ((((size_t)b*NC + Cp)*IMG + (size_t)p*WSZ + Hp)*IMG
                           + (size_t)q*WSZ + Wp);
        *(float4*)op = make_float4(acc[i][0], acc[i][1], acc[i][2], acc[i][3]);
    }
}

extern "C" void kernel_launch(void* const* d_in, const int* in_sizes, int n_in,
                              void* d_out, int out_size)
{
    const float* x  = (const float*)d_in[0];
    const float* Ws = (const float*)d_in[1];
    const float* Hs = (const float*)d_in[2];
    const float* Cs = (const float*)d_in[3];
    float* out = (float*)d_out;

    cudaFuncSetAttribute(k_stage12, cudaFuncAttributeMaxDynamicSharedMemorySize,
                         SM_TOTAL);

    k_prep<<<48, 256>>>(Ws, Hs);

    dim3 gA(64, NC, NB);              // (window, channel, batch) = 12288 CTAs
    k_stage12<<<gA, 128, SM_TOTAL>>>(x);

    dim3 gB(WSZ*WSZ/128, NWIN);
    k_stage3<<<gB, 256>>>(Cs, out);
}

// round 7
// speedup vs baseline: 2.9550x; 1.0994x over previous
#include <cuda_runtime.h>
#include <cuda_bf16.h>
#include <cstdint>

typedef unsigned short ushort_t;

// Problem constants
#define WSZ   64
#define NC    48
#define NT    3
#define NB    4
#define IMG   512
#define KTOT  (NT*NC)            // 144
#define NWIN  (NB*8*8)           // 256

// G scratch, bf16 hi/lo planes: [win][k=(t*48+c)][n=H'*64+W']  (288 MiB each)
__device__ __align__(16) ushort_t Gh[(size_t)NWIN * KTOT * 4096];
__device__ __align__(16) ushort_t Gl[(size_t)NWIN * KTOT * 4096];

// Pre-split, pre-transposed factors (bf16 hi/lo), [t][n][k]
__device__ __align__(16) ushort_t FWh[NT*WSZ*WSZ], FWl[NT*WSZ*WSZ];
__device__ __align__(16) ushort_t FHh[NT*WSZ*WSZ], FHl[NT*WSZ*WSZ];
// Cs^T pre-split: [C'][k=t*48+c]
__device__ __align__(16) ushort_t CsTh[NC*KTOT], CsTl[NC*KTOT];

// ---------------------------------------------------------------------------
// helpers
// ---------------------------------------------------------------------------
__device__ __forceinline__ uint32_t smem_u32(const void* p) {
    uint32_t a;
    asm("{ .reg .u64 t; cvta.to.shared.u64 t, %1; cvt.u32.u64 %0, t; }"
        : "=r"(a) : "l"(p));
    return a;
}
__device__ __forceinline__ void bsplit(float x, ushort_t& h, ushort_t& l) {
    __nv_bfloat16 bh = __float2bfloat16(x);
    float r = x - __bfloat162float(bh);
    __nv_bfloat16 bl = __float2bfloat16(r);
    h = *reinterpret_cast<ushort_t*>(&bh);
    l = *reinterpret_cast<ushort_t*>(&bl);
}
__device__ __forceinline__ void ldsm4(uint32_t* r, uint32_t addr) {
    asm volatile("ldmatrix.sync.aligned.m8n8.x4.shared.b16 {%0,%1,%2,%3}, [%4];"
                 : "=r"(r[0]), "=r"(r[1]), "=r"(r[2]), "=r"(r[3]) : "r"(addr));
}
__device__ __forceinline__ void ldsm4t(uint32_t* r, uint32_t addr) {
    asm volatile("ldmatrix.sync.aligned.m8n8.x4.trans.shared.b16 {%0,%1,%2,%3}, [%4];"
                 : "=r"(r[0]), "=r"(r[1]), "=r"(r[2]), "=r"(r[3]) : "r"(addr));
}
__device__ __forceinline__ void mma16816(float* d, const uint32_t* a,
                                         uint32_t b0, uint32_t b1) {
    asm volatile(
        "mma.sync.aligned.m16n8k16.row.col.f32.bf16.bf16.f32 "
        "{%0,%1,%2,%3},{%4,%5,%6,%7},{%8,%9},{%0,%1,%2,%3};"
        : "+f"(d[0]), "+f"(d[1]), "+f"(d[2]), "+f"(d[3])
        : "r"(a[0]), "r"(a[1]), "r"(a[2]), "r"(a[3]), "r"(b0), "r"(b1));
}

#define RSTRIDE 144   // stage12 smem row stride (bytes per 64-bf16 row)

// 64x64x64 bf16x3 GEMM, warp tile 32x32 (from R6, unchanged)
__device__ __forceinline__ void gemm64_32(
    uint32_t aAh, uint32_t aAl, uint32_t aBh, uint32_t aBl,
    int mrow, int ncol0, int lane, float acc[2][4][4])
{
    const int rA = lane & 15;
    const int cA = (lane >> 4) * 8;
    const int mB = lane >> 3;
    const int nB = (mB >> 1) * 8 + (lane & 7);
    const int kB = (mB & 1) * 8;
    const uint32_t pA0 = (uint32_t)((mrow + rA) * RSTRIDE + cA * 2);
    const uint32_t pA1 = pA0 + 16 * RSTRIDE;
    const uint32_t pB0 = (uint32_t)((ncol0 + nB) * RSTRIDE + kB * 2);
    const uint32_t pB1 = pB0 + 16 * RSTRIDE;

    #pragma unroll
    for (int ks = 0; ks < 4; ks++) {
        const uint32_t ko = ks * 32;
        uint32_t ah0[4], ah1[4], al0[4], al1[4];
        ldsm4(ah0, aAh + pA0 + ko);
        ldsm4(ah1, aAh + pA1 + ko);
        ldsm4(al0, aAl + pA0 + ko);
        ldsm4(al1, aAl + pA1 + ko);
        uint32_t bh0[4], bh1[4], bl0[4], bl1[4];
        ldsm4(bh0, aBh + pB0 + ko);
        ldsm4(bh1, aBh + pB1 + ko);
        ldsm4(bl0, aBl + pB0 + ko);
        ldsm4(bl1, aBl + pB1 + ko);

        mma16816(acc[0][0], ah0, bh0[0], bh0[1]);
        mma16816(acc[0][1], ah0, bh0[2], bh0[3]);
        mma16816(acc[0][2], ah0, bh1[0], bh1[1]);
        mma16816(acc[0][3], ah0, bh1[2], bh1[3]);
        mma16816(acc[1][0], ah1, bh0[0], bh0[1]);
        mma16816(acc[1][1], ah1, bh0[2], bh0[3]);
        mma16816(acc[1][2], ah1, bh1[0], bh1[1]);
        mma16816(acc[1][3], ah1, bh1[2], bh1[3]);

        mma16816(acc[0][0], ah0, bl0[0], bl0[1]);
        mma16816(acc[0][1], ah0, bl0[2], bl0[3]);
        mma16816(acc[0][2], ah0, bl1[0], bl1[1]);
        mma16816(acc[0][3], ah0, bl1[2], bl1[3]);
        mma16816(acc[1][0], ah1, bl0[0], bl0[1]);
        mma16816(acc[1][1], ah1, bl0[2], bl0[3]);
        mma16816(acc[1][2], ah1, bl1[0], bl1[1]);
        mma16816(acc[1][3], ah1, bl1[2], bl1[3]);

        mma16816(acc[0][0], al0, bh0[0], bh0[1]);
        mma16816(acc[0][1], al0, bh0[2], bh0[3]);
        mma16816(acc[0][2], al0, bh1[0], bh1[1]);
        mma16816(acc[0][3], al0, bh1[2], bh1[3]);
        mma16816(acc[1][0], al1, bh0[0], bh0[1]);
        mma16816(acc[1][1], al1, bh0[2], bh0[3]);
        mma16816(acc[1][2], al1, bh1[0], bh1[1]);
        mma16816(acc[1][3], al1, bh1[2], bh1[3]);
    }
}

// ---------------------------------------------------------------------------
// Prep: transpose + split factors; also Cs^T split. Runs once, tiny.
// ---------------------------------------------------------------------------
__global__ void k_prep(const float* __restrict__ Ws, const float* __restrict__ Hs,
                       const float* __restrict__ Cs)
{
    int u = blockIdx.x * 256 + threadIdx.x;
    if (u < NT*WSZ*WSZ) {
        int t = u >> 12;
        int r = u & 4095;
        int k = r >> 6;
        int n = r & 63;
        ushort_t h, l;
        bsplit(Ws[u], h, l);
        FWh[(t << 12) + n*WSZ + k] = h;
        FWl[(t << 12) + n*WSZ + k] = l;
        bsplit(Hs[u], h, l);
        FHh[(t << 12) + n*WSZ + k] = h;
        FHl[(t << 12) + n*WSZ + k] = l;
    }
    if (u < KTOT*NC) {                 // Cs[t][c][C'] flat = [k][C']
        int k  = u / NC;
        int Cp = u % NC;
        ushort_t h, l;
        bsplit(Cs[u], h, l);
        CsTh[Cp*KTOT + k] = h;
        CsTl[Cp*KTOT + k] = l;
    }
}

// stage12 SMEM layout (bytes)
#define OXH 0
#define OXL 9216
#define OTH 18432
#define OTL 27648
#define OFH 36864
#define OFL 46080
#define SM12_TOTAL 55296

// ---------------------------------------------------------------------------
// Stage12 (R6 structure; epilogue2 now writes bf16 hi/lo planes)
// ---------------------------------------------------------------------------
__global__ void __launch_bounds__(128) k_stage12(const float* __restrict__ x)
{
    extern __shared__ __align__(16) char smem[];
    const uint32_t S = smem_u32(smem);
    const uint32_t XH = S+OXH, XL = S+OXL, TH = S+OTH, TL = S+OTL,
                   FH = S+OFH, FL = S+OFL;

    const int tid  = threadIdx.x;
    const int lane = tid & 31;
    const int wid  = tid >> 5;
    const int mrow  = (wid >> 1) * 32;
    const int ncol0 = (wid & 1) * 32;

    const int win = blockIdx.x, c = blockIdx.y, b = blockIdx.z;
    const int q = win & 7, p = win >> 3;

    // Stage X (split once)
    const float* xw = x + (((size_t)(b*NC + c)*IMG + (size_t)p*WSZ)*IMG + (size_t)q*WSZ);
    #pragma unroll
    for (int it = 0; it < 8; it++) {
        int u = it*128 + tid;
        int r = u >> 4, w4 = (u & 15) << 2;
        float4 v = *(const float4*)&xw[(size_t)r*IMG + w4];
        ushort_t h0,l0,h1,l1,h2,l2,h3,l3;
        bsplit(v.x,h0,l0); bsplit(v.y,h1,l1); bsplit(v.z,h2,l2); bsplit(v.w,h3,l3);
        uint32_t off = (uint32_t)(r*RSTRIDE + w4*2);
        *(uint32_t*)(smem + OXH + off)     = (uint32_t)h0 | ((uint32_t)h1 << 16);
        *(uint32_t*)(smem + OXH + off + 4) = (uint32_t)h2 | ((uint32_t)h3 << 16);
        *(uint32_t*)(smem + OXL + off)     = (uint32_t)l0 | ((uint32_t)l1 << 16);
        *(uint32_t*)(smem + OXL + off + 4) = (uint32_t)l2 | ((uint32_t)l3 << 16);
    }

    const size_t winI = (size_t)((b*8 + p)*8 + q);
    const int erow = lane >> 2;
    const int ecol = (lane & 3) * 2;

    for (int t = 0; t < NT; t++) {
        __syncthreads();

        {   // Ws_t^T -> F
            const uint4* sh = (const uint4*)(FWh + (t << 12));
            const uint4* sl = (const uint4*)(FWl + (t << 12));
            #pragma unroll
            for (int i = 0; i < 4; i++) {
                int idx = i*128 + tid;
                uint32_t off = (uint32_t)((idx >> 3)*RSTRIDE + (idx & 7)*16);
                *(uint4*)(smem + OFH + off) = sh[idx];
                *(uint4*)(smem + OFL + off) = sl[idx];
            }
        }
        __syncthreads();

        float acc[2][4][4];
        #pragma unroll
        for (int a1 = 0; a1 < 2; a1++)
            #pragma unroll
            for (int a2 = 0; a2 < 4; a2++)
                #pragma unroll
                for (int a3 = 0; a3 < 4; a3++) acc[a1][a2][a3] = 0.0f;
        gemm64_32(FH, FL, XH, XL, mrow, ncol0, lane, acc);
        __syncthreads();

        // Epilogue1: split acc -> T1 [W'][h]
        #pragma unroll
        for (int mt = 0; mt < 2; mt++)
            #pragma unroll
            for (int g = 0; g < 4; g++) {
                int row = mrow + mt*16 + erow;
                int hc  = ncol0 + g*8 + ecol;
                ushort_t hA,lA,hB,lB;
                bsplit(acc[mt][g][0], hA, lA); bsplit(acc[mt][g][1], hB, lB);
                uint32_t o0 = (uint32_t)(row*RSTRIDE + hc*2);
                *(uint32_t*)(smem + OTH + o0) = (uint32_t)hA | ((uint32_t)hB << 16);
                *(uint32_t*)(smem + OTL + o0) = (uint32_t)lA | ((uint32_t)lB << 16);
                bsplit(acc[mt][g][2], hA, lA); bsplit(acc[mt][g][3], hB, lB);
                uint32_t o1 = o0 + 8*RSTRIDE;
                *(uint32_t*)(smem + OTH + o1) = (uint32_t)hA | ((uint32_t)hB << 16);
                *(uint32_t*)(smem + OTL + o1) = (uint32_t)lA | ((uint32_t)lB << 16);
            }

        {   // Hs_t^T -> F
            const uint4* sh = (const uint4*)(FHh + (t << 12));
            const uint4* sl = (const uint4*)(FHl + (t << 12));
            #pragma unroll
            for (int i = 0; i < 4; i++) {
                int idx = i*128 + tid;
                uint32_t off = (uint32_t)((idx >> 3)*RSTRIDE + (idx & 7)*16);
                *(uint4*)(smem + OFH + off) = sh[idx];
                *(uint4*)(smem + OFL + off) = sl[idx];
            }
        }
        __syncthreads();

        #pragma unroll
        for (int a1 = 0; a1 < 2; a1++)
            #pragma unroll
            for (int a2 = 0; a2 < 4; a2++)
                #pragma unroll
                for (int a3 = 0; a3 < 4; a3++) acc[a1][a2][a3] = 0.0f;
        gemm64_32(FH, FL, TH, TL, mrow, ncol0, lane, acc);

        // Epilogue2: split + store to Gh/Gl [k][H'][W']
        const size_t kbase = (winI*KTOT + (size_t)(t*NC + c)) * 4096;
        ushort_t* gho = Gh + kbase;
        ushort_t* glo = Gl + kbase;
        #pragma unroll
        for (int mt = 0; mt < 2; mt++)
            #pragma unroll
            for (int g = 0; g < 4; g++) {
                int Hp = mrow + mt*16 + erow;
                int Wp = ncol0 + g*8 + ecol;
                ushort_t hA,lA,hB,lB;
                bsplit(acc[mt][g][0], hA, lA); bsplit(acc[mt][g][1], hB, lB);
                *(uint32_t*)&gho[Hp*WSZ + Wp] = (uint32_t)hA | ((uint32_t)hB << 16);
                *(uint32_t*)&glo[Hp*WSZ + Wp] = (uint32_t)lA | ((uint32_t)lB << 16);
                bsplit(acc[mt][g][2], hA, lA); bsplit(acc[mt][g][3], hB, lB);
                *(uint32_t*)&gho[(Hp+8)*WSZ + Wp] = (uint32_t)hA | ((uint32_t)hB << 16);
                *(uint32_t*)&glo[(Hp+8)*WSZ + Wp] = (uint32_t)lA | ((uint32_t)lB << 16);
            }
    }
}

// ---------------------------------------------------------------------------
// Stage3 (tensor): per (window, 256-n tile): out[48][256] = CsT[48][144].G[144][256]
// A resident in SMEM, B chunks of 16 k-rows, ldmatrix.trans for B fragments.
// ---------------------------------------------------------------------------
#define ASTR 336      // A smem row stride bytes (168 bf16)
#define BSTR 528      // B smem row stride bytes (264 bf16)
#define OA3H 0
#define OA3L 16128    // 48*336
#define OB3H 32256
#define OB3L 40704    // +16*528
#define SM3_TOTAL 49152

__global__ void __launch_bounds__(128) k_stage3(float* __restrict__ out)
{
    extern __shared__ __align__(16) char smem[];
    const uint32_t S = smem_u32(smem);
    const uint32_t AH = S+OA3H, AL = S+OA3L, BH = S+OB3H, BL = S+OB3L;

    const int tid  = threadIdx.x;
    const int lane = tid & 31;
    const int wid  = tid >> 5;
    const int win   = blockIdx.y;
    const int ntile = blockIdx.x;         // 0..15, 256 n each
    const int n0 = wid * 64;              // within tile

    // Load CsT (hi/lo) into SMEM: 48 rows x 144 bf16 -> stride 168
    for (int i = tid; i < 864; i += 128) {        // 48*18 uint4
        int r = i / 18, u = i % 18;
        uint32_t off = (uint32_t)(r*ASTR + u*16);
        *(uint4*)(smem + OA3H + off) = *(const uint4*)(CsTh + r*KTOT + u*8);
        *(uint4*)(smem + OA3L + off) = *(const uint4*)(CsTl + r*KTOT + u*8);
    }

    // frag address components
    const int rA = lane & 15;
    const int cA = (lane >> 4) * 8;
    const int rB = (lane & 7) + ((lane >> 3) & 1) * 8;
    const int cB = ((lane >> 4) & 1) * 8;

    float acc[3][8][4];
    #pragma unroll
    for (int i = 0; i < 3; i++)
        #pragma unroll
        for (int j = 0; j < 8; j++)
            #pragma unroll
            for (int k = 0; k < 4; k++) acc[i][j][k] = 0.0f;

    const size_t gbase = (size_t)win * KTOT * 4096 + (size_t)ntile * 256;

    for (int kc = 0; kc < 9; kc++) {
        __syncthreads();   // prev chunk reads done (covers A at kc=0)
        // Load B chunk: 16 k-rows x 256 n, hi+lo
        {
            const ushort_t* gh = Gh + gbase + (size_t)(kc*16) * 4096;
            const ushort_t* gl = Gl + gbase + (size_t)(kc*16) * 4096;
            #pragma unroll
            for (int i = 0; i < 4; i++) {
                int idx = i*128 + tid;           // 0..511
                int kk = idx >> 5, u = idx & 31;
                uint32_t off = (uint32_t)(kk*BSTR + u*16);
                *(uint4*)(smem + OB3H + off) = *(const uint4*)(gh + (size_t)kk*4096 + u*8);
                *(uint4*)(smem + OB3L + off) = *(const uint4*)(gl + (size_t)kk*4096 + u*8);
            }
        }
        __syncthreads();

        // A fragments (k-cols kc*16..): 3 m-tiles, hi+lo
        uint32_t ah[3][4], al[3][4];
        #pragma unroll
        for (int mt = 0; mt < 3; mt++) {
            uint32_t pa = (uint32_t)((mt*16 + rA)*ASTR + (kc*16 + cA)*2);
            ldsm4(ah[mt], AH + pa);
            ldsm4(al[mt], AL + pa);
        }
        // B fragments: 4 ldsm.x4.trans per plane, each covers 2 n8-groups
        uint32_t bh[4][4], bl[4][4];
        #pragma unroll
        for (int ng = 0; ng < 4; ng++) {
            uint32_t pb = (uint32_t)(rB*BSTR + (n0 + ng*16 + cB)*2);
            ldsm4t(bh[ng], BH + pb);
            ldsm4t(bl[ng], BL + pb);
        }

        #pragma unroll
        for (int mt = 0; mt < 3; mt++)
            #pragma unroll
            for (int ng = 0; ng < 4; ng++) {
                mma16816(acc[mt][ng*2  ], ah[mt], bh[ng][0], bh[ng][1]);
                mma16816(acc[mt][ng*2+1], ah[mt], bh[ng][2], bh[ng][3]);
                mma16816(acc[mt][ng*2  ], ah[mt], bl[ng][0], bl[ng][1]);
                mma16816(acc[mt][ng*2+1], ah[mt], bl[ng][2], bl[ng][3]);
                mma16816(acc[mt][ng*2  ], al[mt], bh[ng][0], bh[ng][1]);
                mma16816(acc[mt][ng*2+1], al[mt], bh[ng][2], bh[ng][3]);
            }
    }

    // Epilogue: out[b][C'][p*64+H'][q*64+W']
    const int b = win >> 6;
    const int p = (win >> 3) & 7;
    const int q = win & 7;
    const int Hp = ntile*4 + wid;          // warp's 64 n = one H' row
    const int erow = lane >> 2;
    const int ecol = (lane & 3) * 2;
    #pragma unroll
    for (int mt = 0; mt < 3; mt++)
        #pragma unroll
        for (int g = 0; g < 8; g++) {
            int Wp = g*8 + ecol;
            int Cp = mt*16 + erow;
            float* op = out + ((((size_t)b*NC + Cp)*IMG + (size_t)p*WSZ + Hp)*IMG
                               + (size_t)q*WSZ + Wp);
            *(float2*)op = make_float2(acc[mt][g][0], acc[mt][g][1]);
            float* op2 = op + (size_t)8*IMG*IMG;   // Cp+8
            *(float2*)op2 = make_float2(acc[mt][g][2], acc[mt][g][3]);
        }
}

extern "C" void kernel_launch(void* const* d_in, const int* in_sizes, int n_in,
                              void* d_out, int out_size)
{
    const float* x  = (const float*)d_in[0];
    const float* Ws = (const float*)d_in[1];
    const float* Hs = (const float*)d_in[2];
    const float* Cs = (const float*)d_in[3];
    float* out = (float*)d_out;

    cudaFuncSetAttribute(k_stage12, cudaFuncAttributeMaxDynamicSharedMemorySize,
                         SM12_TOTAL);
    cudaFuncSetAttribute(k_stage3, cudaFuncAttributeMaxDynamicSharedMemorySize,
                         SM3_TOTAL);

    k_prep<<<48, 256>>>(Ws, Hs, Cs);

    dim3 gA(64, NC, NB);                  // 12288 CTAs
    k_stage12<<<gA, 128, SM12_TOTAL>>>(x);

    dim3 gB(16, NWIN);                    // 4096 CTAs
    k_stage3<<<gB, 128, SM3_TOTAL>>>(out);
}

// round 9
// speedup vs baseline: 3.7668x; 1.2747x over previous
#include <cuda_runtime.h>
#include <cuda_bf16.h>
#include <cuda_fp16.h>
#include <cstdint>

typedef unsigned short ushort_t;

// Problem constants
#define WSZ   64
#define NC    48
#define NT    3
#define NB    4
#define IMG   512
#define KTOT  (NT*NC)            // 144
#define NWIN  (NB*8*8)           // 256

// G scratch, single fp16 plane: [win][k=(t*48+c)][n=H'*64+W']  (288 MiB)
__device__ __align__(16) ushort_t Gf[(size_t)NWIN * KTOT * 4096];

// Pre-split, pre-transposed factors (bf16 hi/lo), [t][n][k]
__device__ __align__(16) ushort_t FWh[NT*WSZ*WSZ], FWl[NT*WSZ*WSZ];
__device__ __align__(16) ushort_t FHh[NT*WSZ*WSZ], FHl[NT*WSZ*WSZ];
// Cs^T pre-split fp16 hi/lo: [C'][k=t*48+c]
__device__ __align__(16) ushort_t CsTh[NC*KTOT], CsTl[NC*KTOT];

// ---------------------------------------------------------------------------
// helpers
// ---------------------------------------------------------------------------
__device__ __forceinline__ uint32_t smem_u32(const void* p) {
    uint32_t a;
    asm("{ .reg .u64 t; cvta.to.shared.u64 t, %1; cvt.u32.u64 %0, t; }"
        : "=r"(a) : "l"(p));
    return a;
}
__device__ __forceinline__ void bsplit(float x, ushort_t& h, ushort_t& l) {
    __nv_bfloat16 bh = __float2bfloat16(x);
    float r = x - __bfloat162float(bh);
    __nv_bfloat16 bl = __float2bfloat16(r);
    h = *reinterpret_cast<ushort_t*>(&bh);
    l = *reinterpret_cast<ushort_t*>(&bl);
}
__device__ __forceinline__ void hsplit(float x, ushort_t& h, ushort_t& l) {
    __half hh = __float2half_rn(x);
    float r = x - __half2float(hh);
    __half hl = __float2half_rn(r);
    h = *reinterpret_cast<ushort_t*>(&hh);
    l = *reinterpret_cast<ushort_t*>(&hl);
}
__device__ __forceinline__ void ldsm4(uint32_t* r, uint32_t addr) {
    asm volatile("ldmatrix.sync.aligned.m8n8.x4.shared.b16 {%0,%1,%2,%3}, [%4];"
                 : "=r"(r[0]), "=r"(r[1]), "=r"(r[2]), "=r"(r[3]) : "r"(addr));
}
__device__ __forceinline__ void ldsm4t(uint32_t* r, uint32_t addr) {
    asm volatile("ldmatrix.sync.aligned.m8n8.x4.trans.shared.b16 {%0,%1,%2,%3}, [%4];"
                 : "=r"(r[0]), "=r"(r[1]), "=r"(r[2]), "=r"(r[3]) : "r"(addr));
}
__device__ __forceinline__ void mma16816(float* d, const uint32_t* a,
                                         uint32_t b0, uint32_t b1) {
    asm volatile(
        "mma.sync.aligned.m16n8k16.row.col.f32.bf16.bf16.f32 "
        "{%0,%1,%2,%3},{%4,%5,%6,%7},{%8,%9},{%0,%1,%2,%3};"
        : "+f"(d[0]), "+f"(d[1]), "+f"(d[2]), "+f"(d[3])
        : "r"(a[0]), "r"(a[1]), "r"(a[2]), "r"(a[3]), "r"(b0), "r"(b1));
}
__device__ __forceinline__ void mma16816h(float* d, const uint32_t* a,
                                          uint32_t b0, uint32_t b1) {
    asm volatile(
        "mma.sync.aligned.m16n8k16.row.col.f32.f16.f16.f32 "
        "{%0,%1,%2,%3},{%4,%5,%6,%7},{%8,%9},{%0,%1,%2,%3};"
        : "+f"(d[0]), "+f"(d[1]), "+f"(d[2]), "+f"(d[3])
        : "r"(a[0]), "r"(a[1]), "r"(a[2]), "r"(a[3]), "r"(b0), "r"(b1));
}

#define RSTRIDE 144   // stage12 smem row stride (bytes per 64-bf16 row)

// 64x64x64 bf16x3 GEMM, warp tile 32x32 (unchanged from R6)
__device__ __forceinline__ void gemm64_32(
    uint32_t aAh, uint32_t aAl, uint32_t aBh, uint32_t aBl,
    int mrow, int ncol0, int lane, float acc[2][4][4])
{
    const int rA = lane & 15;
    const int cA = (lane >> 4) * 8;
    const int mB = lane >> 3;
    const int nB = (mB >> 1) * 8 + (lane & 7);
    const int kB = (mB & 1) * 8;
    const uint32_t pA0 = (uint32_t)((mrow + rA) * RSTRIDE + cA * 2);
    const uint32_t pA1 = pA0 + 16 * RSTRIDE;
    const uint32_t pB0 = (uint32_t)((ncol0 + nB) * RSTRIDE + kB * 2);
    const uint32_t pB1 = pB0 + 16 * RSTRIDE;

    #pragma unroll
    for (int ks = 0; ks < 4; ks++) {
        const uint32_t ko = ks * 32;
        uint32_t ah0[4], ah1[4], al0[4], al1[4];
        ldsm4(ah0, aAh + pA0 + ko);
        ldsm4(ah1, aAh + pA1 + ko);
        ldsm4(al0, aAl + pA0 + ko);
        ldsm4(al1, aAl + pA1 + ko);
        uint32_t bh0[4], bh1[4], bl0[4], bl1[4];
        ldsm4(bh0, aBh + pB0 + ko);
        ldsm4(bh1, aBh + pB1 + ko);
        ldsm4(bl0, aBl + pB0 + ko);
        ldsm4(bl1, aBl + pB1 + ko);

        mma16816(acc[0][0], ah0, bh0[0], bh0[1]);
        mma16816(acc[0][1], ah0, bh0[2], bh0[3]);
        mma16816(acc[0][2], ah0, bh1[0], bh1[1]);
        mma16816(acc[0][3], ah0, bh1[2], bh1[3]);
        mma16816(acc[1][0], ah1, bh0[0], bh0[1]);
        mma16816(acc[1][1], ah1, bh0[2], bh0[3]);
        mma16816(acc[1][2], ah1, bh1[0], bh1[1]);
        mma16816(acc[1][3], ah1, bh1[2], bh1[3]);

        mma16816(acc[0][0], ah0, bl0[0], bl0[1]);
        mma16816(acc[0][1], ah0, bl0[2], bl0[3]);
        mma16816(acc[0][2], ah0, bl1[0], bl1[1]);
        mma16816(acc[0][3], ah0, bl1[2], bl1[3]);
        mma16816(acc[1][0], ah1, bl0[0], bl0[1]);
        mma16816(acc[1][1], ah1, bl0[2], bl0[3]);
        mma16816(acc[1][2], ah1, bl1[0], bl1[1]);
        mma16816(acc[1][3], ah1, bl1[2], bl1[3]);

        mma16816(acc[0][0], al0, bh0[0], bh0[1]);
        mma16816(acc[0][1], al0, bh0[2], bh0[3]);
        mma16816(acc[0][2], al0, bh1[0], bh1[1]);
        mma16816(acc[0][3], al0, bh1[2], bh1[3]);
        mma16816(acc[1][0], al1, bh0[0], bh0[1]);
        mma16816(acc[1][1], al1, bh0[2], bh0[3]);
        mma16816(acc[1][2], al1, bh1[0], bh1[1]);
        mma16816(acc[1][3], al1, bh1[2], bh1[3]);
    }
}

// ---------------------------------------------------------------------------
// Prep (once, tiny): factors bf16-split+transposed; Cs^T fp16-split.
// ---------------------------------------------------------------------------
__global__ void k_prep(const float* __restrict__ Ws, const float* __restrict__ Hs,
                       const float* __restrict__ Cs)
{
    int u = blockIdx.x * 256 + threadIdx.x;
    if (u < NT*WSZ*WSZ) {
        int t = u >> 12;
        int r = u & 4095;
        int k = r >> 6;
        int n = r & 63;
        ushort_t h, l;
        bsplit(Ws[u], h, l);
        FWh[(t << 12) + n*WSZ + k] = h;
        FWl[(t << 12) + n*WSZ + k] = l;
        bsplit(Hs[u], h, l);
        FHh[(t << 12) + n*WSZ + k] = h;
        FHl[(t << 12) + n*WSZ + k] = l;
    }
    if (u < KTOT*NC) {                 // Cs[t][c][C'] flat = [k][C']
        int k  = u / NC;
        int Cp = u % NC;
        ushort_t h, l;
        hsplit(Cs[u], h, l);
        CsTh[Cp*KTOT + k] = h;
        CsTl[Cp*KTOT + k] = l;
    }
}

// stage12 SMEM layout (bytes)
#define OXH 0
#define OXL 9216
#define OTH 18432
#define OTL 27648
#define OFH 36864
#define OFL 46080
#define SM12_TOTAL 55296

// ---------------------------------------------------------------------------
// Stage12 (R6/R7 structure; epilogue2 stores fp16 single plane)
// ---------------------------------------------------------------------------
__global__ void __launch_bounds__(128) k_stage12(const float* __restrict__ x)
{
    extern __shared__ __align__(16) char smem[];
    const uint32_t S = smem_u32(smem);
    const uint32_t XH = S+OXH, XL = S+OXL, TH = S+OTH, TL = S+OTL,
                   FH = S+OFH, FL = S+OFL;

    const int tid  = threadIdx.x;
    const int lane = tid & 31;
    const int wid  = tid >> 5;
    const int mrow  = (wid >> 1) * 32;
    const int ncol0 = (wid & 1) * 32;

    const int win = blockIdx.x, c = blockIdx.y, b = blockIdx.z;
    const int q = win & 7, p = win >> 3;

    // Stage X (split once)
    const float* xw = x + (((size_t)(b*NC + c)*IMG + (size_t)p*WSZ)*IMG + (size_t)q*WSZ);
    #pragma unroll
    for (int it = 0; it < 8; it++) {
        int u = it*128 + tid;
        int r = u >> 4, w4 = (u & 15) << 2;
        float4 v = *(const float4*)&xw[(size_t)r*IMG + w4];
        ushort_t h0,l0,h1,l1,h2,l2,h3,l3;
        bsplit(v.x,h0,l0); bsplit(v.y,h1,l1); bsplit(v.z,h2,l2); bsplit(v.w,h3,l3);
        uint32_t off = (uint32_t)(r*RSTRIDE + w4*2);
        *(uint32_t*)(smem + OXH + off)     = (uint32_t)h0 | ((uint32_t)h1 << 16);
        *(uint32_t*)(smem + OXH + off + 4) = (uint32_t)h2 | ((uint32_t)h3 << 16);
        *(uint32_t*)(smem + OXL + off)     = (uint32_t)l0 | ((uint32_t)l1 << 16);
        *(uint32_t*)(smem + OXL + off + 4) = (uint32_t)l2 | ((uint32_t)l3 << 16);
    }

    const size_t winI = (size_t)((b*8 + p)*8 + q);
    const int erow = lane >> 2;
    const int ecol = (lane & 3) * 2;

    for (int t = 0; t < NT; t++) {
        __syncthreads();

        {   // Ws_t^T -> F
            const uint4* sh = (const uint4*)(FWh + (t << 12));
            const uint4* sl = (const uint4*)(FWl + (t << 12));
            #pragma unroll
            for (int i = 0; i < 4; i++) {
                int idx = i*128 + tid;
                uint32_t off = (uint32_t)((idx >> 3)*RSTRIDE + (idx & 7)*16);
                *(uint4*)(smem + OFH + off) = sh[idx];
                *(uint4*)(smem + OFL + off) = sl[idx];
            }
        }
        __syncthreads();

        float acc[2][4][4];
        #pragma unroll
        for (int a1 = 0; a1 < 2; a1++)
            #pragma unroll
            for (int a2 = 0; a2 < 4; a2++)
                #pragma unroll
                for (int a3 = 0; a3 < 4; a3++) acc[a1][a2][a3] = 0.0f;
        gemm64_32(FH, FL, XH, XL, mrow, ncol0, lane, acc);
        __syncthreads();

        // Epilogue1: split acc -> T1 [W'][h]
        #pragma unroll
        for (int mt = 0; mt < 2; mt++)
            #pragma unroll
            for (int g = 0; g < 4; g++) {
                int row = mrow + mt*16 + erow;
                int hc  = ncol0 + g*8 + ecol;
                ushort_t hA,lA,hB,lB;
                bsplit(acc[mt][g][0], hA, lA); bsplit(acc[mt][g][1], hB, lB);
                uint32_t o0 = (uint32_t)(row*RSTRIDE + hc*2);
                *(uint32_t*)(smem + OTH + o0) = (uint32_t)hA | ((uint32_t)hB << 16);
                *(uint32_t*)(smem + OTL + o0) = (uint32_t)lA | ((uint32_t)lB << 16);
                bsplit(acc[mt][g][2], hA, lA); bsplit(acc[mt][g][3], hB, lB);
                uint32_t o1 = o0 + 8*RSTRIDE;
                *(uint32_t*)(smem + OTH + o1) = (uint32_t)hA | ((uint32_t)hB << 16);
                *(uint32_t*)(smem + OTL + o1) = (uint32_t)lA | ((uint32_t)lB << 16);
            }

        {   // Hs_t^T -> F
            const uint4* sh = (const uint4*)(FHh + (t << 12));
            const uint4* sl = (const uint4*)(FHl + (t << 12));
            #pragma unroll
            for (int i = 0; i < 4; i++) {
                int idx = i*128 + tid;
                uint32_t off = (uint32_t)((idx >> 3)*RSTRIDE + (idx & 7)*16);
                *(uint4*)(smem + OFH + off) = sh[idx];
                *(uint4*)(smem + OFL + off) = sl[idx];
            }
        }
        __syncthreads();

        #pragma unroll
        for (int a1 = 0; a1 < 2; a1++)
            #pragma unroll
            for (int a2 = 0; a2 < 4; a2++)
                #pragma unroll
                for (int a3 = 0; a3 < 4; a3++) acc[a1][a2][a3] = 0.0f;
        gemm64_32(FH, FL, TH, TL, mrow, ncol0, lane, acc);

        // Epilogue2: convert fp16 + store single plane G[k][H'][W']
        ushort_t* gf = Gf + (winI*KTOT + (size_t)(t*NC + c)) * 4096;
        #pragma unroll
        for (int mt = 0; mt < 2; mt++)
            #pragma unroll
            for (int g = 0; g < 4; g++) {
                int Hp = mrow + mt*16 + erow;
                int Wp = ncol0 + g*8 + ecol;
                __half2 v01 = __floats2half2_rn(acc[mt][g][0], acc[mt][g][1]);
                __half2 v23 = __floats2half2_rn(acc[mt][g][2], acc[mt][g][3]);
                *(uint32_t*)&gf[Hp*WSZ + Wp]     = *(uint32_t*)&v01;
                *(uint32_t*)&gf[(Hp+8)*WSZ + Wp] = *(uint32_t*)&v23;
            }
    }
}

// ---------------------------------------------------------------------------
// Stage3 (fp16 tensor): per (window, 256-n tile):
//   out[48][256] = CsT[48][144] . G[144][256]
// A (fp16 hi/lo) resident; B single fp16 plane, ping-pong + register prefetch.
// ---------------------------------------------------------------------------
#define ASTR 336      // A smem row stride bytes (168 fp16)
#define BSTR 528      // B smem row stride bytes (264 fp16)
#define BBUF 8448     // 16 rows * BSTR
#define OA3H 0
#define OA3L 16128    // 48*336
#define OB3  32256    // two buffers: +0 / +BBUF
#define SM3_TOTAL (OB3 + 2*BBUF)   // 49152

__global__ void __launch_bounds__(128) k_stage3(float* __restrict__ out)
{
    extern __shared__ __align__(16) char smem[];
    const uint32_t S = smem_u32(smem);
    const uint32_t AH = S+OA3H, AL = S+OA3L, B0 = S+OB3;

    const int tid  = threadIdx.x;
    const int lane = tid & 31;
    const int wid  = tid >> 5;
    const int win   = blockIdx.y;
    const int ntile = blockIdx.x;         // 0..15, 256 n each
    const int n0 = wid * 64;

    // Load CsT (fp16 hi/lo): 48 rows x 144 -> 18 uint4 per row
    for (int i = tid; i < 864; i += 128) {
        int r = i / 18, u = i % 18;
        uint32_t off = (uint32_t)(r*ASTR + u*16);
        *(uint4*)(smem + OA3H + off) = *(const uint4*)(CsTh + r*KTOT + u*8);
        *(uint4*)(smem + OA3L + off) = *(const uint4*)(CsTl + r*KTOT + u*8);
    }

    const size_t gbase = (size_t)win * KTOT * 4096 + (size_t)ntile * 256;
    const ushort_t* gf = Gf + gbase;

    // chunk-load coords: rows lk0, lk0+4, lk0+8, lk0+12 ; 32 uint4 per row
    const int lk0 = tid >> 5;
    const int lu  = (tid & 31);

    // Preload chunk 0 into buffer 0 (pointer-based stores)
    #pragma unroll
    for (int i = 0; i < 4; i++) {
        int kk = lk0 + i*4;
        *(uint4*)(smem + OB3 + (uint32_t)(kk*BSTR + lu*16)) =
            *(const uint4*)(gf + (size_t)kk*4096 + lu*8);
    }
    __syncthreads();

    // frag address components
    const int rA = lane & 15;
    const int cA = (lane >> 4) * 8;
    const int rB = (lane & 7) + ((lane >> 3) & 1) * 8;
    const int cB = ((lane >> 4) & 1) * 8;

    float acc[3][8][4];
    #pragma unroll
    for (int i = 0; i < 3; i++)
        #pragma unroll
        for (int j = 0; j < 8; j++)
            #pragma unroll
            for (int k = 0; k < 4; k++) acc[i][j][k] = 0.0f;

    for (int kc = 0; kc < 9; kc++) {
        // Prefetch next chunk to registers
        uint4 pf[4];
        if (kc < 8) {
            const ushort_t* gn = gf + (size_t)((kc+1)*16) * 4096;
            #pragma unroll
            for (int i = 0; i < 4; i++)
                pf[i] = *(const uint4*)(gn + (size_t)(lk0 + i*4)*4096 + lu*8);
        }

        // A fragments (k-cols kc*16..)
        uint32_t ah[3][4], al[3][4];
        #pragma unroll
        for (int mt = 0; mt < 3; mt++) {
            uint32_t pa = (uint32_t)((mt*16 + rA)*ASTR + (kc*16 + cA)*2);
            ldsm4(ah[mt], AH + pa);
            ldsm4(al[mt], AL + pa);
        }
        // B fragments from current buffer (u32 addr OK for ldmatrix only)
        const uint32_t Bc = B0 + (uint32_t)((kc & 1) * BBUF);
        uint32_t bf[4][4];
        #pragma unroll
        for (int ng = 0; ng < 4; ng++)
            ldsm4t(bf[ng], Bc + (uint32_t)(rB*BSTR + (n0 + ng*16 + cB)*2));

        #pragma unroll
        for (int mt = 0; mt < 3; mt++)
            #pragma unroll
            for (int ng = 0; ng < 4; ng++) {
                mma16816h(acc[mt][ng*2  ], ah[mt], bf[ng][0], bf[ng][1]);
                mma16816h(acc[mt][ng*2+1], ah[mt], bf[ng][2], bf[ng][3]);
                mma16816h(acc[mt][ng*2  ], al[mt], bf[ng][0], bf[ng][1]);
                mma16816h(acc[mt][ng*2+1], al[mt], bf[ng][2], bf[ng][3]);
            }

        if (kc < 8) {
            // Store prefetched chunk through REAL pointers (generic space)
            char* Bn = smem + OB3 + ((kc+1) & 1) * BBUF;
            #pragma unroll
            for (int i = 0; i < 4; i++)
                *(uint4*)(Bn + (uint32_t)((lk0 + i*4)*BSTR + lu*16)) = pf[i];
            __syncthreads();
        }
    }

    // Epilogue: out[b][C'][p*64+H'][q*64+W']
    const int b = win >> 6;
    const int p = (win >> 3) & 7;
    const int q = win & 7;
    const int Hp = ntile*4 + wid;
    const int erow = lane >> 2;
    const int ecol = (lane & 3) * 2;
    #pragma unroll
    for (int mt = 0; mt < 3; mt++)
        #pragma unroll
        for (int g = 0; g < 8; g++) {
            int Wp = g*8 + ecol;
            int Cp = mt*16 + erow;
            float* op = out + ((((size_t)b*NC + Cp)*IMG + (size_t)p*WSZ + Hp)*IMG
                               + (size_t)q*WSZ + Wp);
            *(float2*)op = make_float2(acc[mt][g][0], acc[mt][g][1]);
            float* op2 = op + (size_t)8*IMG*IMG;   // Cp+8
            *(float2*)op2 = make_float2(acc[mt][g][2], acc[mt][g][3]);
        }
}

extern "C" void kernel_launch(void* const* d_in, const int* in_sizes, int n_in,
                              void* d_out, int out_size)
{
    const float* x  = (const float*)d_in[0];
    const float* Ws = (const float*)d_in[1];
    const float* Hs = (const float*)d_in[2];
    const float* Cs = (const float*)d_in[3];
    float* out = (float*)d_out;

    cudaFuncSetAttribute(k_stage12, cudaFuncAttributeMaxDynamicSharedMemorySize,
                         SM12_TOTAL);
    cudaFuncSetAttribute(k_stage3, cudaFuncAttributeMaxDynamicSharedMemorySize,
                         SM3_TOTAL);

    k_prep<<<48, 256>>>(Ws, Hs, Cs);

    dim3 gA(64, NC, NB);                  // 12288 CTAs
    k_stage12<<<gA, 128, SM12_TOTAL>>>(x);

    dim3 gB(16, NWIN);                    // 4096 CTAs
    k_stage3<<<gB, 128, SM3_TOTAL>>>(out);
}

// round 10
// speedup vs baseline: 4.3006x; 1.1417x over previous
#include <cuda_runtime.h>
#include <cuda_bf16.h>
#include <cuda_fp16.h>
#include <cstdint>

typedef unsigned short ushort_t;

// Problem constants
#define WSZ   64
#define NC    48
#define NT    3
#define NB    4
#define IMG   512
#define KTOT  (NT*NC)            // 144
#define NWIN  (NB*8*8)           // 256

// G scratch, single fp16 plane: [win][k=(t*48+c)][n=H'*64+W']  (288 MiB)
__device__ __align__(16) ushort_t Gf[(size_t)NWIN * KTOT * 4096];

// Pre-split, pre-transposed factors (fp16 hi/lo), [t][n][k]
__device__ __align__(16) ushort_t FWh[NT*WSZ*WSZ], FWl[NT*WSZ*WSZ];
__device__ __align__(16) ushort_t FHh[NT*WSZ*WSZ], FHl[NT*WSZ*WSZ];
// Cs^T pre-split fp16 hi/lo: [C'][k=t*48+c]
__device__ __align__(16) ushort_t CsTh[NC*KTOT], CsTl[NC*KTOT];

// ---------------------------------------------------------------------------
// helpers
// ---------------------------------------------------------------------------
__device__ __forceinline__ uint32_t smem_u32(const void* p) {
    uint32_t a;
    asm("{ .reg .u64 t; cvta.to.shared.u64 t, %1; cvt.u32.u64 %0, t; }"
        : "=r"(a) : "l"(p));
    return a;
}
__device__ __forceinline__ void hsplit(float x, ushort_t& h, ushort_t& l) {
    __half hh = __float2half_rn(x);
    float r = x - __half2float(hh);
    __half hl = __float2half_rn(r);
    h = *reinterpret_cast<ushort_t*>(&hh);
    l = *reinterpret_cast<ushort_t*>(&hl);
}
__device__ __forceinline__ void ldsm4(uint32_t* r, uint32_t addr) {
    asm volatile("ldmatrix.sync.aligned.m8n8.x4.shared.b16 {%0,%1,%2,%3}, [%4];"
                 : "=r"(r[0]), "=r"(r[1]), "=r"(r[2]), "=r"(r[3]) : "r"(addr));
}
__device__ __forceinline__ void ldsm4t(uint32_t* r, uint32_t addr) {
    asm volatile("ldmatrix.sync.aligned.m8n8.x4.trans.shared.b16 {%0,%1,%2,%3}, [%4];"
                 : "=r"(r[0]), "=r"(r[1]), "=r"(r[2]), "=r"(r[3]) : "r"(addr));
}
__device__ __forceinline__ void mma16816h(float* d, const uint32_t* a,
                                          uint32_t b0, uint32_t b1) {
    asm volatile(
        "mma.sync.aligned.m16n8k16.row.col.f32.f16.f16.f32 "
        "{%0,%1,%2,%3},{%4,%5,%6,%7},{%8,%9},{%0,%1,%2,%3};"
        : "+f"(d[0]), "+f"(d[1]), "+f"(d[2]), "+f"(d[3])
        : "r"(a[0]), "r"(a[1]), "r"(a[2]), "r"(a[3]), "r"(b0), "r"(b1));
}

#define RSTRIDE 144   // stage12 smem row stride (bytes per 64-fp16 row)

// 64x64x64 fp16x2 GEMM (A = hi/lo fp16, B = single fp16), warp tile 32x32.
__device__ __forceinline__ void gemm64_32h(
    uint32_t aAh, uint32_t aAl, uint32_t aB,
    int mrow, int ncol0, int lane, float acc[2][4][4])
{
    const int rA = lane & 15;
    const int cA = (lane >> 4) * 8;
    const int mB = lane >> 3;
    const int nB = (mB >> 1) * 8 + (lane & 7);
    const int kB = (mB & 1) * 8;
    const uint32_t pA0 = (uint32_t)((mrow + rA) * RSTRIDE + cA * 2);
    const uint32_t pA1 = pA0 + 16 * RSTRIDE;
    const uint32_t pB0 = (uint32_t)((ncol0 + nB) * RSTRIDE + kB * 2);
    const uint32_t pB1 = pB0 + 16 * RSTRIDE;

    #pragma unroll
    for (int ks = 0; ks < 4; ks++) {
        const uint32_t ko = ks * 32;
        uint32_t ah0[4], ah1[4], al0[4], al1[4];
        ldsm4(ah0, aAh + pA0 + ko);
        ldsm4(ah1, aAh + pA1 + ko);
        ldsm4(al0, aAl + pA0 + ko);
        ldsm4(al1, aAl + pA1 + ko);
        uint32_t b0[4], b1[4];
        ldsm4(b0, aB + pB0 + ko);
        ldsm4(b1, aB + pB1 + ko);

        mma16816h(acc[0][0], ah0, b0[0], b0[1]);
        mma16816h(acc[0][1], ah0, b0[2], b0[3]);
        mma16816h(acc[0][2], ah0, b1[0], b1[1]);
        mma16816h(acc[0][3], ah0, b1[2], b1[3]);
        mma16816h(acc[1][0], ah1, b0[0], b0[1]);
        mma16816h(acc[1][1], ah1, b0[2], b0[3]);
        mma16816h(acc[1][2], ah1, b1[0], b1[1]);
        mma16816h(acc[1][3], ah1, b1[2], b1[3]);

        mma16816h(acc[0][0], al0, b0[0], b0[1]);
        mma16816h(acc[0][1], al0, b0[2], b0[3]);
        mma16816h(acc[0][2], al0, b1[0], b1[1]);
        mma16816h(acc[0][3], al0, b1[2], b1[3]);
        mma16816h(acc[1][0], al1, b0[0], b0[1]);
        mma16816h(acc[1][1], al1, b0[2], b0[3]);
        mma16816h(acc[1][2], al1, b1[0], b1[1]);
        mma16816h(acc[1][3], al1, b1[2], b1[3]);
    }
}

// ---------------------------------------------------------------------------
// Prep (once, tiny): factors fp16-split+transposed; Cs^T fp16-split.
// ---------------------------------------------------------------------------
__global__ void k_prep(const float* __restrict__ Ws, const float* __restrict__ Hs,
                       const float* __restrict__ Cs)
{
    int u = blockIdx.x * 256 + threadIdx.x;
    if (u < NT*WSZ*WSZ) {
        int t = u >> 12;
        int r = u & 4095;
        int k = r >> 6;
        int n = r & 63;
        ushort_t h, l;
        hsplit(Ws[u], h, l);
        FWh[(t << 12) + n*WSZ + k] = h;
        FWl[(t << 12) + n*WSZ + k] = l;
        hsplit(Hs[u], h, l);
        FHh[(t << 12) + n*WSZ + k] = h;
        FHl[(t << 12) + n*WSZ + k] = l;
    }
    if (u < KTOT*NC) {                 // Cs[t][c][C'] flat = [k][C']
        int k  = u / NC;
        int Cp = u % NC;
        ushort_t h, l;
        hsplit(Cs[u], h, l);
        CsTh[Cp*KTOT + k] = h;
        CsTl[Cp*KTOT + k] = l;
    }
}

// stage12 SMEM layout (bytes): X single, T1 single, F hi/lo
#define OX  0
#define OT  9216
#define OFH 18432
#define OFL 27648
#define SM12_TOTAL 36864

// ---------------------------------------------------------------------------
// Stage12 (fp16x2 tensor): per (b,c,window), per t:
//   GEMM1: tmp1^T[W'][h] = Ws^T(hi/lo) . X(fp16)
//   GEMM2: tmp2 [H'][W'] = Hs^T(hi/lo) . tmp1^T(fp16)
// ---------------------------------------------------------------------------
__global__ void __launch_bounds__(128) k_stage12(const float* __restrict__ x)
{
    extern __shared__ __align__(16) char smem[];
    const uint32_t S = smem_u32(smem);
    const uint32_t XS = S+OX, TS = S+OT, FH = S+OFH, FL = S+OFL;

    const int tid  = threadIdx.x;
    const int lane = tid & 31;
    const int wid  = tid >> 5;
    const int mrow  = (wid >> 1) * 32;
    const int ncol0 = (wid & 1) * 32;

    const int win = blockIdx.x, c = blockIdx.y, b = blockIdx.z;
    const int q = win & 7, p = win >> 3;

    // Stage X once as single fp16 plane [h][w]
    const float* xw = x + (((size_t)(b*NC + c)*IMG + (size_t)p*WSZ)*IMG + (size_t)q*WSZ);
    #pragma unroll
    for (int it = 0; it < 8; it++) {
        int u = it*128 + tid;
        int r = u >> 4, w4 = (u & 15) << 2;
        float4 v = *(const float4*)&xw[(size_t)r*IMG + w4];
        __half2 v01 = __floats2half2_rn(v.x, v.y);
        __half2 v23 = __floats2half2_rn(v.z, v.w);
        uint32_t off = (uint32_t)(r*RSTRIDE + w4*2);
        *(uint32_t*)(smem + OX + off)     = *(uint32_t*)&v01;
        *(uint32_t*)(smem + OX + off + 4) = *(uint32_t*)&v23;
    }

    const size_t winI = (size_t)((b*8 + p)*8 + q);
    const int erow = lane >> 2;
    const int ecol = (lane & 3) * 2;

    for (int t = 0; t < NT; t++) {
        __syncthreads();   // prev t's F/T1 reads complete

        {   // Ws_t^T (fp16 hi/lo) -> F
            const uint4* sh = (const uint4*)(FWh + (t << 12));
            const uint4* sl = (const uint4*)(FWl + (t << 12));
            #pragma unroll
            for (int i = 0; i < 4; i++) {
                int idx = i*128 + tid;
                uint32_t off = (uint32_t)((idx >> 3)*RSTRIDE + (idx & 7)*16);
                *(uint4*)(smem + OFH + off) = sh[idx];
                *(uint4*)(smem + OFL + off) = sl[idx];
            }
        }
        __syncthreads();

        float acc[2][4][4];
        #pragma unroll
        for (int a1 = 0; a1 < 2; a1++)
            #pragma unroll
            for (int a2 = 0; a2 < 4; a2++)
                #pragma unroll
                for (int a3 = 0; a3 < 4; a3++) acc[a1][a2][a3] = 0.0f;
        gemm64_32h(FH, FL, XS, mrow, ncol0, lane, acc);
        __syncthreads();   // all F(Ws)/X reads done

        // Epilogue1: convert acc -> T1 [W'][h] single fp16
        #pragma unroll
        for (int mt = 0; mt < 2; mt++)
            #pragma unroll
            for (int g = 0; g < 4; g++) {
                int row = mrow + mt*16 + erow;
                int hc  = ncol0 + g*8 + ecol;
                __half2 v01 = __floats2half2_rn(acc[mt][g][0], acc[mt][g][1]);
                __half2 v23 = __floats2half2_rn(acc[mt][g][2], acc[mt][g][3]);
                uint32_t o0 = (uint32_t)(row*RSTRIDE + hc*2);
                *(uint32_t*)(smem + OT + o0)             = *(uint32_t*)&v01;
                *(uint32_t*)(smem + OT + o0 + 8*RSTRIDE) = *(uint32_t*)&v23;
            }

        {   // Hs_t^T (fp16 hi/lo) -> F
            const uint4* sh = (const uint4*)(FHh + (t << 12));
            const uint4* sl = (const uint4*)(FHl + (t << 12));
            #pragma unroll
            for (int i = 0; i < 4; i++) {
                int idx = i*128 + tid;
                uint32_t off = (uint32_t)((idx >> 3)*RSTRIDE + (idx & 7)*16);
                *(uint4*)(smem + OFH + off) = sh[idx];
                *(uint4*)(smem + OFL + off) = sl[idx];
            }
        }
        __syncthreads();   // T1 + F(Hs) ready

        #pragma unroll
        for (int a1 = 0; a1 < 2; a1++)
            #pragma unroll
            for (int a2 = 0; a2 < 4; a2++)
                #pragma unroll
                for (int a3 = 0; a3 < 4; a3++) acc[a1][a2][a3] = 0.0f;
        gemm64_32h(FH, FL, TS, mrow, ncol0, lane, acc);

        // Epilogue2: convert fp16 + store single plane G[k][H'][W']
        ushort_t* gf = Gf + (winI*KTOT + (size_t)(t*NC + c)) * 4096;
        #pragma unroll
        for (int mt = 0; mt < 2; mt++)
            #pragma unroll
            for (int g = 0; g < 4; g++) {
                int Hp = mrow + mt*16 + erow;
                int Wp = ncol0 + g*8 + ecol;
                __half2 v01 = __floats2half2_rn(acc[mt][g][0], acc[mt][g][1]);
                __half2 v23 = __floats2half2_rn(acc[mt][g][2], acc[mt][g][3]);
                *(uint32_t*)&gf[Hp*WSZ + Wp]     = *(uint32_t*)&v01;
                *(uint32_t*)&gf[(Hp+8)*WSZ + Wp] = *(uint32_t*)&v23;
            }
    }
}

// ---------------------------------------------------------------------------
// Stage3 (fp16 tensor, unchanged from R9): per (window, 256-n tile):
//   out[48][256] = CsT[48][144] . G[144][256]
// ---------------------------------------------------------------------------
#define ASTR 336
#define BSTR 528
#define BBUF 8448
#define OA3H 0
#define OA3L 16128
#define OB3  32256
#define SM3_TOTAL (OB3 + 2*BBUF)   // 49152

__global__ void __launch_bounds__(128) k_stage3(float* __restrict__ out)
{
    extern __shared__ __align__(16) char smem[];
    const uint32_t S = smem_u32(smem);
    const uint32_t AH = S+OA3H, AL = S+OA3L, B0 = S+OB3;

    const int tid  = threadIdx.x;
    const int lane = tid & 31;
    const int wid  = tid >> 5;
    const int win   = blockIdx.y;
    const int ntile = blockIdx.x;
    const int n0 = wid * 64;

    for (int i = tid; i < 864; i += 128) {
        int r = i / 18, u = i % 18;
        uint32_t off = (uint32_t)(r*ASTR + u*16);
        *(uint4*)(smem + OA3H + off) = *(const uint4*)(CsTh + r*KTOT + u*8);
        *(uint4*)(smem + OA3L + off) = *(const uint4*)(CsTl + r*KTOT + u*8);
    }

    const size_t gbase = (size_t)win * KTOT * 4096 + (size_t)ntile * 256;
    const ushort_t* gf = Gf + gbase;

    const int lk0 = tid >> 5;
    const int lu  = (tid & 31);

    #pragma unroll
    for (int i = 0; i < 4; i++) {
        int kk = lk0 + i*4;
        *(uint4*)(smem + OB3 + (uint32_t)(kk*BSTR + lu*16)) =
            *(const uint4*)(gf + (size_t)kk*4096 + lu*8);
    }
    __syncthreads();

    const int rA = lane & 15;
    const int cA = (lane >> 4) * 8;
    const int rB = (lane & 7) + ((lane >> 3) & 1) * 8;
    const int cB = ((lane >> 4) & 1) * 8;

    float acc[3][8][4];
    #pragma unroll
    for (int i = 0; i < 3; i++)
        #pragma unroll
        for (int j = 0; j < 8; j++)
            #pragma unroll
            for (int k = 0; k < 4; k++) acc[i][j][k] = 0.0f;

    for (int kc = 0; kc < 9; kc++) {
        uint4 pf[4];
        if (kc < 8) {
            const ushort_t* gn = gf + (size_t)((kc+1)*16) * 4096;
            #pragma unroll
            for (int i = 0; i < 4; i++)
                pf[i] = *(const uint4*)(gn + (size_t)(lk0 + i*4)*4096 + lu*8);
        }

        uint32_t ah[3][4], al[3][4];
        #pragma unroll
        for (int mt = 0; mt < 3; mt++) {
            uint32_t pa = (uint32_t)((mt*16 + rA)*ASTR + (kc*16 + cA)*2);
            ldsm4(ah[mt], AH + pa);
            ldsm4(al[mt], AL + pa);
        }
        const uint32_t Bc = B0 + (uint32_t)((kc & 1) * BBUF);
        uint32_t bf[4][4];
        #pragma unroll
        for (int ng = 0; ng < 4; ng++)
            ldsm4t(bf[ng], Bc + (uint32_t)(rB*BSTR + (n0 + ng*16 + cB)*2));

        #pragma unroll
        for (int mt = 0; mt < 3; mt++)
            #pragma unroll
            for (int ng = 0; ng < 4; ng++) {
                mma16816h(acc[mt][ng*2  ], ah[mt], bf[ng][0], bf[ng][1]);
                mma16816h(acc[mt][ng*2+1], ah[mt], bf[ng][2], bf[ng][3]);
                mma16816h(acc[mt][ng*2  ], al[mt], bf[ng][0], bf[ng][1]);
                mma16816h(acc[mt][ng*2+1], al[mt], bf[ng][2], bf[ng][3]);
            }

        if (kc < 8) {
            char* Bn = smem + OB3 + ((kc+1) & 1) * BBUF;
            #pragma unroll
            for (int i = 0; i < 4; i++)
                *(uint4*)(Bn + (uint32_t)((lk0 + i*4)*BSTR + lu*16)) = pf[i];
            __syncthreads();
        }
    }

    const int b = win >> 6;
    const int p = (win >> 3) & 7;
    const int q = win & 7;
    const int Hp = ntile*4 + wid;
    const int erow = lane >> 2;
    const int ecol = (lane & 3) * 2;
    #pragma unroll
    for (int mt = 0; mt < 3; mt++)
        #pragma unroll
        for (int g = 0; g < 8; g++) {
            int Wp = g*8 + ecol;
            int Cp = mt*16 + erow;
            float* op = out + ((((size_t)b*NC + Cp)*IMG + (size_t)p*WSZ + Hp)*IMG
                               + (size_t)q*WSZ + Wp);
            *(float2*)op = make_float2(acc[mt][g][0], acc[mt][g][1]);
            float* op2 = op + (size_t)8*IMG*IMG;
            *(float2*)op2 = make_float2(acc[mt][g][2], acc[mt][g][3]);
        }
}

extern "C" void kernel_launch(void* const* d_in, const int* in_sizes, int n_in,
                              void* d_out, int out_size)
{
    const float* x  = (const float*)d_in[0];
    const float* Ws = (const float*)d_in[1];
    const float* Hs = (const float*)d_in[2];
    const float* Cs = (const float*)d_in[3];
    float* out = (float*)d_out;

    cudaFuncSetAttribute(k_stage12, cudaFuncAttributeMaxDynamicSharedMemorySize,
                         SM12_TOTAL);
    cudaFuncSetAttribute(k_stage3, cudaFuncAttributeMaxDynamicSharedMemorySize,
                         SM3_TOTAL);

    k_prep<<<48, 256>>>(Ws, Hs, Cs);

    dim3 gA(64, NC, NB);                  // 12288 CTAs
    k_stage12<<<gA, 128, SM12_TOTAL>>>(x);

    dim3 gB(16, NWIN);                    // 4096 CTAs
    k_stage3<<<gB, 128, SM3_TOTAL>>>(out);
}

// round 11
// speedup vs baseline: 5.1358x; 1.1942x over previous
#include <cuda_runtime.h>
#include <cuda_fp16.h>
#include <cstdint>

typedef unsigned short ushort_t;

// Problem constants
#define WSZ   64
#define NC    48
#define NT    3
#define NB    4
#define IMG   512
#define KTOT  (NT*NC)            // 144
#define NWIN  (NB*8*8)           // 256

// G scratch, single fp16 plane: [win][k=(t*48+c)][n=H'*64+W']  (288 MiB)
__device__ __align__(16) ushort_t Gf[(size_t)NWIN * KTOT * 4096];

// Pre-split, pre-transposed factors (fp16 hi/lo), [t][n][k]
__device__ __align__(16) ushort_t FWh[NT*WSZ*WSZ], FWl[NT*WSZ*WSZ];
__device__ __align__(16) ushort_t FHh[NT*WSZ*WSZ], FHl[NT*WSZ*WSZ];
// Cs^T single fp16: [C'][k=t*48+c]
__device__ __align__(16) ushort_t CsTh[NC*KTOT];

// ---------------------------------------------------------------------------
// helpers
// ---------------------------------------------------------------------------
__device__ __forceinline__ uint32_t smem_u32(const void* p) {
    uint32_t a;
    asm("{ .reg .u64 t; cvta.to.shared.u64 t, %1; cvt.u32.u64 %0, t; }"
        : "=r"(a) : "l"(p));
    return a;
}
__device__ __forceinline__ void hsplit(float x, ushort_t& h, ushort_t& l) {
    __half hh = __float2half_rn(x);
    float r = x - __half2float(hh);
    __half hl = __float2half_rn(r);
    h = *reinterpret_cast<ushort_t*>(&hh);
    l = *reinterpret_cast<ushort_t*>(&hl);
}
__device__ __forceinline__ void ldsm4(uint32_t* r, uint32_t addr) {
    asm volatile("ldmatrix.sync.aligned.m8n8.x4.shared.b16 {%0,%1,%2,%3}, [%4];"
                 : "=r"(r[0]), "=r"(r[1]), "=r"(r[2]), "=r"(r[3]) : "r"(addr));
}
__device__ __forceinline__ void ldsm4t(uint32_t* r, uint32_t addr) {
    asm volatile("ldmatrix.sync.aligned.m8n8.x4.trans.shared.b16 {%0,%1,%2,%3}, [%4];"
                 : "=r"(r[0]), "=r"(r[1]), "=r"(r[2]), "=r"(r[3]) : "r"(addr));
}
__device__ __forceinline__ void mma16816h(float* d, const uint32_t* a,
                                          uint32_t b0, uint32_t b1) {
    asm volatile(
        "mma.sync.aligned.m16n8k16.row.col.f32.f16.f16.f32 "
        "{%0,%1,%2,%3},{%4,%5,%6,%7},{%8,%9},{%0,%1,%2,%3};"
        : "+f"(d[0]), "+f"(d[1]), "+f"(d[2]), "+f"(d[3])
        : "r"(a[0]), "r"(a[1]), "r"(a[2]), "r"(a[3]), "r"(b0), "r"(b1));
}
__device__ __forceinline__ void cpa16(uint32_t dst, const void* src) {
    asm volatile("cp.async.ca.shared.global [%0], [%1], 16;"
                 :: "r"(dst), "l"(src) : "memory");
}
#define CPA_COMMIT() asm volatile("cp.async.commit_group;" ::: "memory")

#define RSTRIDE 144   // stage12 smem row stride (bytes per 64-fp16 row)

// MxNxK = 64x(<=128)x64 fp16x2 GEMM (A hi/lo, B single), warp tile 32x32.
__device__ __forceinline__ void gemm64_32h(
    uint32_t aAh, uint32_t aAl, uint32_t aB,
    int mrow, int ncol0, int lane, float acc[2][4][4])
{
    const int rA = lane & 15;
    const int cA = (lane >> 4) * 8;
    const int mB = lane >> 3;
    const int nB = (mB >> 1) * 8 + (lane & 7);
    const int kB = (mB & 1) * 8;
    const uint32_t pA0 = (uint32_t)((mrow + rA) * RSTRIDE + cA * 2);
    const uint32_t pA1 = pA0 + 16 * RSTRIDE;
    const uint32_t pB0 = (uint32_t)((ncol0 + nB) * RSTRIDE + kB * 2);
    const uint32_t pB1 = pB0 + 16 * RSTRIDE;

    #pragma unroll
    for (int ks = 0; ks < 4; ks++) {
        const uint32_t ko = ks * 32;
        uint32_t ah0[4], ah1[4], al0[4], al1[4];
        ldsm4(ah0, aAh + pA0 + ko);
        ldsm4(ah1, aAh + pA1 + ko);
        ldsm4(al0, aAl + pA0 + ko);
        ldsm4(al1, aAl + pA1 + ko);
        uint32_t b0[4], b1[4];
        ldsm4(b0, aB + pB0 + ko);
        ldsm4(b1, aB + pB1 + ko);

        mma16816h(acc[0][0], ah0, b0[0], b0[1]);
        mma16816h(acc[0][1], ah0, b0[2], b0[3]);
        mma16816h(acc[0][2], ah0, b1[0], b1[1]);
        mma16816h(acc[0][3], ah0, b1[2], b1[3]);
        mma16816h(acc[1][0], ah1, b0[0], b0[1]);
        mma16816h(acc[1][1], ah1, b0[2], b0[3]);
        mma16816h(acc[1][2], ah1, b1[0], b1[1]);
        mma16816h(acc[1][3], ah1, b1[2], b1[3]);

        mma16816h(acc[0][0], al0, b0[0], b0[1]);
        mma16816h(acc[0][1], al0, b0[2], b0[3]);
        mma16816h(acc[0][2], al0, b1[0], b1[1]);
        mma16816h(acc[0][3], al0, b1[2], b1[3]);
        mma16816h(acc[1][0], al1, b0[0], b0[1]);
        mma16816h(acc[1][1], al1, b0[2], b0[3]);
        mma16816h(acc[1][2], al1, b1[0], b1[1]);
        mma16816h(acc[1][3], al1, b1[2], b1[3]);
    }
}

// ---------------------------------------------------------------------------
// Prep (once, tiny)
// ---------------------------------------------------------------------------
__global__ void k_prep(const float* __restrict__ Ws, const float* __restrict__ Hs,
                       const float* __restrict__ Cs)
{
    int u = blockIdx.x * 256 + threadIdx.x;
    if (u < NT*WSZ*WSZ) {
        int t = u >> 12;
        int r = u & 4095;
        int k = r >> 6;
        int n = r & 63;
        ushort_t h, l;
        hsplit(Ws[u], h, l);
        FWh[(t << 12) + n*WSZ + k] = h;
        FWl[(t << 12) + n*WSZ + k] = l;
        hsplit(Hs[u], h, l);
        FHh[(t << 12) + n*WSZ + k] = h;
        FHl[(t << 12) + n*WSZ + k] = l;
    }
    if (u < KTOT*NC) {                 // Cs flat = [k][C']
        int k  = u / NC;
        int Cp = u % NC;
        __half v = __float2half_rn(Cs[u]);
        CsTh[Cp*KTOT + k] = *reinterpret_cast<ushort_t*>(&v);
    }
}

// stage12 SMEM (bytes): X2 128xRSTRIDE, T2 128xRSTRIDE, F hi/lo 64xRSTRIDE
#define OX2 0
#define OT2 18432
#define OFH12 36864
#define OFL12 46080
#define SM12_TOTAL 55296

// ---------------------------------------------------------------------------
// Stage12: CTA = (b, channel-pair, window). 8 warps. Per t:
//   GEMM1: D1[W'][(cc,h)]   = Ws_t^T(hi/lo) . X2        (M=64,N=128,K=64)
//   GEMM2: D2[H'][(cc,W')]  = Hs_t^T(hi/lo) . T2        (M=64,N=128,K=64)
// ---------------------------------------------------------------------------
__global__ void __launch_bounds__(256) k_stage12(const float* __restrict__ x)
{
    extern __shared__ __align__(16) char smem[];
    const uint32_t S = smem_u32(smem);
    const uint32_t XS = S+OX2, TS = S+OT2, FH = S+OFH12, FL = S+OFL12;

    const int tid  = threadIdx.x;
    const int lane = tid & 31;
    const int wid  = tid >> 5;
    const int mrow  = (wid >> 2) * 32;   // 2 m-tiles
    const int ncol0 = (wid & 3) * 32;    // 4 n-tiles

    const int win = blockIdx.x, cp = blockIdx.y, b = blockIdx.z;
    const int q = win & 7, p = win >> 3;
    const int c0 = cp * 2;

    // Stage X2 (2 channels) once as fp16: rows r=(cc,h)
    #pragma unroll
    for (int it = 0; it < 8; it++) {
        int u = it*256 + tid;            // float4 idx 0..2047
        int r = u >> 4, w4 = (u & 15) << 2;
        int cc = r >> 6, h = r & 63;
        const float* src = x + (((size_t)(b*NC + c0 + cc)*IMG + p*WSZ + h)*IMG
                                + q*WSZ + w4);
        float4 v = *(const float4*)src;
        __half2 v01 = __floats2half2_rn(v.x, v.y);
        __half2 v23 = __floats2half2_rn(v.z, v.w);
        uint32_t off = (uint32_t)(r*RSTRIDE + w4*2);
        *(uint32_t*)(smem + OX2 + off)     = *(uint32_t*)&v01;
        *(uint32_t*)(smem + OX2 + off + 4) = *(uint32_t*)&v23;
    }

    const size_t winI = (size_t)((b*8 + p)*8 + q);
    const int erow = lane >> 2;
    const int ecol = (lane & 3) * 2;

    for (int t = 0; t < NT; t++) {
        __syncthreads();   // prev t's F/T2 reads complete (X2 ready at t=0)

        {   // Ws_t^T (hi/lo) -> F  (512 uint4 per plane / 256 threads)
            const uint4* sh = (const uint4*)(FWh + (t << 12));
            const uint4* sl = (const uint4*)(FWl + (t << 12));
            #pragma unroll
            for (int i = 0; i < 2; i++) {
                int idx = i*256 + tid;
                uint32_t off = (uint32_t)((idx >> 3)*RSTRIDE + (idx & 7)*16);
                *(uint4*)(smem + OFH12 + off) = sh[idx];
                *(uint4*)(smem + OFL12 + off) = sl[idx];
            }
        }
        __syncthreads();

        float acc[2][4][4];
        #pragma unroll
        for (int a1 = 0; a1 < 2; a1++)
            #pragma unroll
            for (int a2 = 0; a2 < 4; a2++)
                #pragma unroll
                for (int a3 = 0; a3 < 4; a3++) acc[a1][a2][a3] = 0.0f;
        gemm64_32h(FH, FL, XS, mrow, ncol0, lane, acc);
        __syncthreads();   // all F(Ws)/X2 reads done

        // Epilogue1: D1[W'=m][(cc,h)=n] -> T2[(cc,W')][h] fp16
        #pragma unroll
        for (int mt = 0; mt < 2; mt++)
            #pragma unroll
            for (int g = 0; g < 4; g++) {
                int m = mrow + mt*16 + erow;           // W'
                int n = ncol0 + g*8 + ecol;
                int cc = n >> 6, h = n & 63;
                __half2 v01 = __floats2half2_rn(acc[mt][g][0], acc[mt][g][1]);
                __half2 v23 = __floats2half2_rn(acc[mt][g][2], acc[mt][g][3]);
                uint32_t o = (uint32_t)((cc*64 + m)*RSTRIDE + h*2);
                *(uint32_t*)(smem + OT2 + o)             = *(uint32_t*)&v01;
                *(uint32_t*)(smem + OT2 + o + 8*RSTRIDE) = *(uint32_t*)&v23;
            }

        {   // Hs_t^T (hi/lo) -> F
            const uint4* sh = (const uint4*)(FHh + (t << 12));
            const uint4* sl = (const uint4*)(FHl + (t << 12));
            #pragma unroll
            for (int i = 0; i < 2; i++) {
                int idx = i*256 + tid;
                uint32_t off = (uint32_t)((idx >> 3)*RSTRIDE + (idx & 7)*16);
                *(uint4*)(smem + OFH12 + off) = sh[idx];
                *(uint4*)(smem + OFL12 + off) = sl[idx];
            }
        }
        __syncthreads();   // T2 + F(Hs) ready

        #pragma unroll
        for (int a1 = 0; a1 < 2; a1++)
            #pragma unroll
            for (int a2 = 0; a2 < 4; a2++)
                #pragma unroll
                for (int a3 = 0; a3 < 4; a3++) acc[a1][a2][a3] = 0.0f;
        gemm64_32h(FH, FL, TS, mrow, ncol0, lane, acc);

        // Epilogue2: D2[H'=m][(cc,W')=n] -> Gf[(t,c0+cc)][H'][W'] fp16
        #pragma unroll
        for (int mt = 0; mt < 2; mt++)
            #pragma unroll
            for (int g = 0; g < 4; g++) {
                int m = mrow + mt*16 + erow;           // H'
                int n = ncol0 + g*8 + ecol;
                int cc = n >> 6, Wp = n & 63;
                ushort_t* gf = Gf + (winI*KTOT + (size_t)(t*NC + c0 + cc)) * 4096;
                __half2 v01 = __floats2half2_rn(acc[mt][g][0], acc[mt][g][1]);
                __half2 v23 = __floats2half2_rn(acc[mt][g][2], acc[mt][g][3]);
                *(uint32_t*)&gf[m*WSZ + Wp]     = *(uint32_t*)&v01;
                *(uint32_t*)&gf[(m+8)*WSZ + Wp] = *(uint32_t*)&v23;
            }
    }
}

// ---------------------------------------------------------------------------
// Stage3: per (window, 256-n tile): out[48][256] = CsT[48][144] . G[144][256]
// A single fp16 resident; B via 3-deep cp.async pipeline. 8 warps, n=32/warp.
// ---------------------------------------------------------------------------
#define ASTR3 336      // A smem row stride bytes (fits 144 fp16 + pad)
#define BSTR 528
#define BBUF 8448      // 16 rows * BSTR
#define OA3 0          // 48*336 = 16128
#define OB3 16128
#define SM3_TOTAL (OB3 + 3*BBUF)   // 41472

__global__ void __launch_bounds__(256) k_stage3(float* __restrict__ out)
{
    extern __shared__ __align__(16) char smem[];
    const uint32_t S = smem_u32(smem);
    const uint32_t AH = S+OA3, B0 = S+OB3;

    const int tid  = threadIdx.x;
    const int lane = tid & 31;
    const int wid  = tid >> 5;            // 0..7
    const int win   = blockIdx.y;
    const int ntile = blockIdx.x;         // 0..15
    // warp covers 32 n: local rows (wid>>1)*64 + (wid&1)*32
    const int nloc = (wid >> 1) * 64 + (wid & 1) * 32;

    // A load: 48 rows x 18 uint4 (single fp16 plane)
    for (int i = tid; i < 864; i += 256) {
        int r = i / 18, u = i % 18;
        *(uint4*)(smem + OA3 + (uint32_t)(r*ASTR3 + u*16)) =
            *(const uint4*)(CsTh + r*KTOT + u*8);
    }

    const size_t gbase = (size_t)win * KTOT * 4096 + (size_t)ntile * 256;
    const ushort_t* gf = Gf + gbase;

    // chunk issue coords: 512 uint4 per chunk / 256 threads = 2 each
    const int k0a = tid >> 5,        lua = tid & 31;          // part 1
    const int k0b = (tid + 256) >> 5, lub = tid & 31;         // part 2 (rows 8..15)

    // Prologue: issue chunks 0,1
    #pragma unroll
    for (int j = 0; j < 2; j++) {
        uint32_t Bd = B0 + (uint32_t)(j * BBUF);
        cpa16(Bd + (uint32_t)(k0a*BSTR + lua*16), gf + (size_t)(j*16 + k0a)*4096 + lua*8);
        cpa16(Bd + (uint32_t)(k0b*BSTR + lub*16), gf + (size_t)(j*16 + k0b)*4096 + lub*8);
        CPA_COMMIT();
    }
    __syncthreads();   // A stores visible (cp.async handled by wait_group)

    const int rA = lane & 15;
    const int cA = (lane >> 4) * 8;
    const int rB = (lane & 7) + ((lane >> 3) & 1) * 8;
    const int cB = ((lane >> 4) & 1) * 8;

    float acc[3][4][4];
    #pragma unroll
    for (int i = 0; i < 3; i++)
        #pragma unroll
        for (int j = 0; j < 4; j++)
            #pragma unroll
            for (int k = 0; k < 4; k++) acc[i][j][k] = 0.0f;

    for (int kc = 0; kc < 9; kc++) {
        if (kc < 8) asm volatile("cp.async.wait_group 1;" ::: "memory");
        else        asm volatile("cp.async.wait_group 0;" ::: "memory");
        __syncthreads();   // chunk kc visible to all threads

        // issue chunk kc+2 (buffer (kc+2)%3 — its old consumer finished)
        if (kc <= 6) {
            int j = kc + 2;
            uint32_t Bd = B0 + (uint32_t)((j % 3) * BBUF);
            cpa16(Bd + (uint32_t)(k0a*BSTR + lua*16), gf + (size_t)(j*16 + k0a)*4096 + lua*8);
            cpa16(Bd + (uint32_t)(k0b*BSTR + lub*16), gf + (size_t)(j*16 + k0b)*4096 + lub*8);
            CPA_COMMIT();
        }

        // A fragments (3 m-tiles, single plane)
        uint32_t a[3][4];
        #pragma unroll
        for (int mt = 0; mt < 3; mt++)
            ldsm4(a[mt], AH + (uint32_t)((mt*16 + rA)*ASTR3 + (kc*16 + cA)*2));
        // B fragments (2 ldsm.x4.trans covering warp's 32 n)
        const uint32_t Bc = B0 + (uint32_t)((kc % 3) * BBUF);
        uint32_t bf[2][4];
        #pragma unroll
        for (int ng = 0; ng < 2; ng++)
            ldsm4t(bf[ng], Bc + (uint32_t)(rB*BSTR + (nloc + ng*16 + cB)*2));

        #pragma unroll
        for (int mt = 0; mt < 3; mt++)
            #pragma unroll
            for (int ng = 0; ng < 2; ng++) {
                mma16816h(acc[mt][ng*2  ], a[mt], bf[ng][0], bf[ng][1]);
                mma16816h(acc[mt][ng*2+1], a[mt], bf[ng][2], bf[ng][3]);
            }
    }

    // Epilogue: out[b][C'][p*64+H'][q*64+W']
    const int b = win >> 6;
    const int p = (win >> 3) & 7;
    const int q = win & 7;
    const int Hp = ntile*4 + (wid >> 1);
    const int erow = lane >> 2;
    const int ecol = (lane & 3) * 2;
    #pragma unroll
    for (int mt = 0; mt < 3; mt++)
        #pragma unroll
        for (int g = 0; g < 4; g++) {
            int Wp = (wid & 1)*32 + g*8 + ecol;
            int Cp = mt*16 + erow;
            float* op = out + ((((size_t)b*NC + Cp)*IMG + (size_t)p*WSZ + Hp)*IMG
                               + (size_t)q*WSZ + Wp);
            *(float2*)op = make_float2(acc[mt][g][0], acc[mt][g][1]);
            float* op2 = op + (size_t)8*IMG*IMG;   // Cp+8
            *(float2*)op2 = make_float2(acc[mt][g][2], acc[mt][g][3]);
        }
}

extern "C" void kernel_launch(void* const* d_in, const int* in_sizes, int n_in,
                              void* d_out, int out_size)
{
    const float* x  = (const float*)d_in[0];
    const float* Ws = (const float*)d_in[1];
    const float* Hs = (const float*)d_in[2];
    const float* Cs = (const float*)d_in[3];
    float* out = (float*)d_out;

    cudaFuncSetAttribute(k_stage12, cudaFuncAttributeMaxDynamicSharedMemorySize,
                         SM12_TOTAL);
    cudaFuncSetAttribute(k_stage3, cudaFuncAttributeMaxDynamicSharedMemorySize,
                         SM3_TOTAL);

    k_prep<<<48, 256>>>(Ws, Hs, Cs);

    dim3 gA(64, NC/2, NB);                // 6144 CTAs, 256 threads
    k_stage12<<<gA, 256, SM12_TOTAL>>>(x);

    dim3 gB(16, NWIN);                    // 4096 CTAs, 256 threads
    k_stage3<<<gB, 256, SM3_TOTAL>>>(out);
}

// round 12
// speedup vs baseline: 6.5456x; 1.2745x over previous
#include <cuda_runtime.h>
#include <cuda_fp16.h>
#include <cstdint>

typedef unsigned short ushort_t;

// Problem constants
#define WSZ   64
#define NC    48
#define NT    3
#define NB    4
#define IMG   512
#define KTOT  (NT*NC)            // 144
#define NWIN  (NB*8*8)           // 256

// G scratch, single fp16 plane: [win][k=(t*48+c)][n=H'*64+W']  (288 MiB)
__device__ __align__(16) ushort_t Gf[(size_t)NWIN * KTOT * 4096];

// Pre-transposed factors, single fp16: [t][n][k]
__device__ __align__(16) ushort_t FWs[NT*WSZ*WSZ];
__device__ __align__(16) ushort_t FHs[NT*WSZ*WSZ];
// Cs^T single fp16: [C'][k=t*48+c]
__device__ __align__(16) ushort_t CsTh[NC*KTOT];

// ---------------------------------------------------------------------------
// helpers
// ---------------------------------------------------------------------------
__device__ __forceinline__ uint32_t smem_u32(const void* p) {
    uint32_t a;
    asm("{ .reg .u64 t; cvta.to.shared.u64 t, %1; cvt.u32.u64 %0, t; }"
        : "=r"(a) : "l"(p));
    return a;
}
__device__ __forceinline__ void ldsm4(uint32_t* r, uint32_t addr) {
    asm volatile("ldmatrix.sync.aligned.m8n8.x4.shared.b16 {%0,%1,%2,%3}, [%4];"
                 : "=r"(r[0]), "=r"(r[1]), "=r"(r[2]), "=r"(r[3]) : "r"(addr));
}
__device__ __forceinline__ void ldsm4t(uint32_t* r, uint32_t addr) {
    asm volatile("ldmatrix.sync.aligned.m8n8.x4.trans.shared.b16 {%0,%1,%2,%3}, [%4];"
                 : "=r"(r[0]), "=r"(r[1]), "=r"(r[2]), "=r"(r[3]) : "r"(addr));
}
__device__ __forceinline__ void mma16816h(float* d, const uint32_t* a,
                                          uint32_t b0, uint32_t b1) {
    asm volatile(
        "mma.sync.aligned.m16n8k16.row.col.f32.f16.f16.f32 "
        "{%0,%1,%2,%3},{%4,%5,%6,%7},{%8,%9},{%0,%1,%2,%3};"
        : "+f"(d[0]), "+f"(d[1]), "+f"(d[2]), "+f"(d[3])
        : "r"(a[0]), "r"(a[1]), "r"(a[2]), "r"(a[3]), "r"(b0), "r"(b1));
}
__device__ __forceinline__ void cpa16(uint32_t dst, const void* src) {
    asm volatile("cp.async.ca.shared.global [%0], [%1], 16;"
                 :: "r"(dst), "l"(src) : "memory");
}
#define CPA_COMMIT() asm volatile("cp.async.commit_group;" ::: "memory")

#define RSTRIDE 144   // smem row stride (bytes per 64-fp16 row)

// Warp GEMM: 32(m) x 32(n) x 64(k), single fp16 A/B, fp32 acc.
// A row-major [m][k] at aA; B [n][k] at aB (both stride RSTRIDE).
__device__ __forceinline__ void gemm32x32(
    uint32_t aA, uint32_t aB, int mrow, int nbase, int lane, float acc[2][4][4])
{
    const int rA = lane & 15;
    const int cA = (lane >> 4) * 8;
    const int mB = lane >> 3;
    const int nB = (mB >> 1) * 8 + (lane & 7);
    const int kB = (mB & 1) * 8;
    const uint32_t pA0 = (uint32_t)((mrow + rA) * RSTRIDE + cA * 2);
    const uint32_t pA1 = pA0 + 16 * RSTRIDE;
    const uint32_t pB0 = (uint32_t)((nbase + nB) * RSTRIDE + kB * 2);
    const uint32_t pB1 = pB0 + 16 * RSTRIDE;

    #pragma unroll
    for (int ks = 0; ks < 4; ks++) {
        const uint32_t ko = ks * 32;
        uint32_t a0[4], a1[4], b0[4], b1[4];
        ldsm4(a0, aA + pA0 + ko);
        ldsm4(a1, aA + pA1 + ko);
        ldsm4(b0, aB + pB0 + ko);
        ldsm4(b1, aB + pB1 + ko);

        mma16816h(acc[0][0], a0, b0[0], b0[1]);
        mma16816h(acc[0][1], a0, b0[2], b0[3]);
        mma16816h(acc[0][2], a0, b1[0], b1[1]);
        mma16816h(acc[0][3], a0, b1[2], b1[3]);
        mma16816h(acc[1][0], a1, b0[0], b0[1]);
        mma16816h(acc[1][1], a1, b0[2], b0[3]);
        mma16816h(acc[1][2], a1, b1[0], b1[1]);
        mma16816h(acc[1][3], a1, b1[2], b1[3]);
    }
}

// ---------------------------------------------------------------------------
// Prep (once, tiny): factors fp16 + transposed; Cs^T fp16.
// ---------------------------------------------------------------------------
__global__ void k_prep(const float* __restrict__ Ws, const float* __restrict__ Hs,
                       const float* __restrict__ Cs)
{
    int u = blockIdx.x * 256 + threadIdx.x;
    if (u < NT*WSZ*WSZ) {
        int t = u >> 12;
        int r = u & 4095;
        int k = r >> 6;
        int n = r & 63;
        __half w = __float2half_rn(Ws[u]);
        __half h = __float2half_rn(Hs[u]);
        FWs[(t << 12) + n*WSZ + k] = *reinterpret_cast<ushort_t*>(&w);
        FHs[(t << 12) + n*WSZ + k] = *reinterpret_cast<ushort_t*>(&h);
    }
    if (u < KTOT*NC) {                 // Cs flat = [k][C']
        int k  = u / NC;
        int Cp = u % NC;
        __half v = __float2half_rn(Cs[u]);
        CsTh[Cp*KTOT + k] = *reinterpret_cast<ushort_t*>(&v);
    }
}

// stage12 SMEM (bytes): X4 256 rows, T4 256 rows, F 64 rows (all RSTRIDE)
#define OX4 0
#define OT4 36864
#define OF12 73728
#define SM12_TOTAL 82944

// ---------------------------------------------------------------------------
// Stage12: CTA = (b, channel-quad, window). 8 warps. Per t:
//   GEMM1: D1[W'][(cc,h)]  = Ws_t^T . X4   (M=64, N=256, K=64)
//   GEMM2: D2[H'][(cc,W')] = Hs_t^T . T4   (M=64, N=256, K=64)
// Warp covers 32m x 64n as two 32x32 halves (epilogue per half).
// ---------------------------------------------------------------------------
__global__ void __launch_bounds__(256) k_stage12(const float* __restrict__ x)
{
    extern __shared__ __align__(16) char smem[];
    const uint32_t S = smem_u32(smem);
    const uint32_t XS = S+OX4, TS = S+OT4, FS = S+OF12;

    const int tid  = threadIdx.x;
    const int lane = tid & 31;
    const int wid  = tid >> 5;
    const int mrow  = (wid >> 2) * 32;       // 2 m-tiles of 32
    const int ncol0 = (wid & 3) * 64;        // 4 n-tiles of 64

    const int win = blockIdx.x, cq = blockIdx.y, b = blockIdx.z;
    const int q = win & 7, p = win >> 3;
    const int c0 = cq * 4;

    // Stage X4 (4 channels) once as fp16: rows r=(cc,h)
    #pragma unroll
    for (int it = 0; it < 16; it++) {
        int u = it*256 + tid;                // float4 idx 0..4095
        int r = u >> 4, w4 = (u & 15) << 2;
        int cc = r >> 6, h = r & 63;
        const float* src = x + (((size_t)(b*NC + c0 + cc)*IMG + p*WSZ + h)*IMG
                                + q*WSZ + w4);
        float4 v = *(const float4*)src;
        __half2 v01 = __floats2half2_rn(v.x, v.y);
        __half2 v23 = __floats2half2_rn(v.z, v.w);
        uint32_t off = (uint32_t)(r*RSTRIDE + w4*2);
        *(uint32_t*)(smem + OX4 + off)     = *(uint32_t*)&v01;
        *(uint32_t*)(smem + OX4 + off + 4) = *(uint32_t*)&v23;
    }

    const size_t winI = (size_t)((b*8 + p)*8 + q);
    const int erow = lane >> 2;
    const int ecol = (lane & 3) * 2;

    for (int t = 0; t < NT; t++) {
        __syncthreads();   // prev t's F/T4 reads complete (X4 ready at t=0)

        {   // Ws_t^T -> F (512 uint4 / 256 threads)
            const uint4* sw = (const uint4*)(FWs + (t << 12));
            #pragma unroll
            for (int i = 0; i < 2; i++) {
                int idx = i*256 + tid;
                *(uint4*)(smem + OF12 + (uint32_t)((idx >> 3)*RSTRIDE + (idx & 7)*16))
                    = sw[idx];
            }
        }
        __syncthreads();

        // GEMM1 (two 32x32 halves per warp) + epilogue1 per half
        #pragma unroll
        for (int half = 0; half < 2; half++) {
            const int nbase = ncol0 + half*32;
            float acc[2][4][4];
            #pragma unroll
            for (int a1 = 0; a1 < 2; a1++)
                #pragma unroll
                for (int a2 = 0; a2 < 4; a2++)
                    #pragma unroll
                    for (int a3 = 0; a3 < 4; a3++) acc[a1][a2][a3] = 0.0f;
            gemm32x32(FS, XS, mrow, nbase, lane, acc);

            // D1[W'=m][(cc,h)=n] -> T4[(cc,W')][h]; cc constant per (warp,half)
            const int cc = nbase >> 6;
            const int hb = nbase & 63;
            #pragma unroll
            for (int mt = 0; mt < 2; mt++)
                #pragma unroll
                for (int g = 0; g < 4; g++) {
                    int m = mrow + mt*16 + erow;       // W'
                    int h = hb + g*8 + ecol;
                    __half2 v01 = __floats2half2_rn(acc[mt][g][0], acc[mt][g][1]);
                    __half2 v23 = __floats2half2_rn(acc[mt][g][2], acc[mt][g][3]);
                    uint32_t o = (uint32_t)((cc*64 + m)*RSTRIDE + h*2);
                    *(uint32_t*)(smem + OT4 + o)             = *(uint32_t*)&v01;
                    *(uint32_t*)(smem + OT4 + o + 8*RSTRIDE) = *(uint32_t*)&v23;
                }
        }
        __syncthreads();   // T4 complete; F(Ws)/X4 reads done

        {   // Hs_t^T -> F
            const uint4* sh = (const uint4*)(FHs + (t << 12));
            #pragma unroll
            for (int i = 0; i < 2; i++) {
                int idx = i*256 + tid;
                *(uint4*)(smem + OF12 + (uint32_t)((idx >> 3)*RSTRIDE + (idx & 7)*16))
                    = sh[idx];
            }
        }
        __syncthreads();

        // GEMM2 + epilogue2 per half
        #pragma unroll
        for (int half = 0; half < 2; half++) {
            const int nbase = ncol0 + half*32;
            float acc[2][4][4];
            #pragma unroll
            for (int a1 = 0; a1 < 2; a1++)
                #pragma unroll
                for (int a2 = 0; a2 < 4; a2++)
                    #pragma unroll
                    for (int a3 = 0; a3 < 4; a3++) acc[a1][a2][a3] = 0.0f;
            gemm32x32(FS, TS, mrow, nbase, lane, acc);

            // D2[H'=m][(cc,W')=n] -> Gf[(t,c0+cc)][H'][W']
            const int cc = nbase >> 6;
            const int wb = nbase & 63;
            ushort_t* gf = Gf + (winI*KTOT + (size_t)(t*NC + c0 + cc)) * 4096;
            #pragma unroll
            for (int mt = 0; mt < 2; mt++)
                #pragma unroll
                for (int g = 0; g < 4; g++) {
                    int m = mrow + mt*16 + erow;       // H'
                    int Wp = wb + g*8 + ecol;
                    __half2 v01 = __floats2half2_rn(acc[mt][g][0], acc[mt][g][1]);
                    __half2 v23 = __floats2half2_rn(acc[mt][g][2], acc[mt][g][3]);
                    *(uint32_t*)&gf[m*WSZ + Wp]     = *(uint32_t*)&v01;
                    *(uint32_t*)&gf[(m+8)*WSZ + Wp] = *(uint32_t*)&v23;
                }
        }
    }
}

// ---------------------------------------------------------------------------
// Stage3 (unchanged R11): per (window, 256-n tile):
//   out[48][256] = CsT[48][144] . G[144][256], 3-deep cp.async pipeline.
// ---------------------------------------------------------------------------
#define ASTR3 336
#define BSTR 528
#define BBUF 8448
#define OA3 0
#define OB3 16128
#define SM3_TOTAL (OB3 + 3*BBUF)   // 41472

__global__ void __launch_bounds__(256) k_stage3(float* __restrict__ out)
{
    extern __shared__ __align__(16) char smem[];
    const uint32_t S = smem_u32(smem);
    const uint32_t AH = S+OA3, B0 = S+OB3;

    const int tid  = threadIdx.x;
    const int lane = tid & 31;
    const int wid  = tid >> 5;
    const int win   = blockIdx.y;
    const int ntile = blockIdx.x;
    const int nloc = (wid >> 1) * 64 + (wid & 1) * 32;

    for (int i = tid; i < 864; i += 256) {
        int r = i / 18, u = i % 18;
        *(uint4*)(smem + OA3 + (uint32_t)(r*ASTR3 + u*16)) =
            *(const uint4*)(CsTh + r*KTOT + u*8);
    }

    const size_t gbase = (size_t)win * KTOT * 4096 + (size_t)ntile * 256;
    const ushort_t* gf = Gf + gbase;

    const int k0a = tid >> 5,         lua = tid & 31;
    const int k0b = (tid + 256) >> 5, lub = tid & 31;

    #pragma unroll
    for (int j = 0; j < 2; j++) {
        uint32_t Bd = B0 + (uint32_t)(j * BBUF);
        cpa16(Bd + (uint32_t)(k0a*BSTR + lua*16), gf + (size_t)(j*16 + k0a)*4096 + lua*8);
        cpa16(Bd + (uint32_t)(k0b*BSTR + lub*16), gf + (size_t)(j*16 + k0b)*4096 + lub*8);
        CPA_COMMIT();
    }
    __syncthreads();

    const int rA = lane & 15;
    const int cA = (lane >> 4) * 8;
    const int rB = (lane & 7) + ((lane >> 3) & 1) * 8;
    const int cB = ((lane >> 4) & 1) * 8;

    float acc[3][4][4];
    #pragma unroll
    for (int i = 0; i < 3; i++)
        #pragma unroll
        for (int j = 0; j < 4; j++)
            #pragma unroll
            for (int k = 0; k < 4; k++) acc[i][j][k] = 0.0f;

    for (int kc = 0; kc < 9; kc++) {
        if (kc < 8) asm volatile("cp.async.wait_group 1;" ::: "memory");
        else        asm volatile("cp.async.wait_group 0;" ::: "memory");
        __syncthreads();

        if (kc <= 6) {
            int j = kc + 2;
            uint32_t Bd = B0 + (uint32_t)((j % 3) * BBUF);
            cpa16(Bd + (uint32_t)(k0a*BSTR + lua*16), gf + (size_t)(j*16 + k0a)*4096 + lua*8);
            cpa16(Bd + (uint32_t)(k0b*BSTR + lub*16), gf + (size_t)(j*16 + k0b)*4096 + lub*8);
            CPA_COMMIT();
        }

        uint32_t a[3][4];
        #pragma unroll
        for (int mt = 0; mt < 3; mt++)
            ldsm4(a[mt], AH + (uint32_t)((mt*16 + rA)*ASTR3 + (kc*16 + cA)*2));
        const uint32_t Bc = B0 + (uint32_t)((kc % 3) * BBUF);
        uint32_t bf[2][4];
        #pragma unroll
        for (int ng = 0; ng < 2; ng++)
            ldsm4t(bf[ng], Bc + (uint32_t)(rB*BSTR + (nloc + ng*16 + cB)*2));

        #pragma unroll
        for (int mt = 0; mt < 3; mt++)
            #pragma unroll
            for (int ng = 0; ng < 2; ng++) {
                mma16816h(acc[mt][ng*2  ], a[mt], bf[ng][0], bf[ng][1]);
                mma16816h(acc[mt][ng*2+1], a[mt], bf[ng][2], bf[ng][3]);
            }
    }

    const int b = win >> 6;
    const int p = (win >> 3) & 7;
    const int q = win & 7;
    const int Hp = ntile*4 + (wid >> 1);
    const int erow = lane >> 2;
    const int ecol = (lane & 3) * 2;
    #pragma unroll
    for (int mt = 0; mt < 3; mt++)
        #pragma unroll
        for (int g = 0; g < 4; g++) {
            int Wp = (wid & 1)*32 + g*8 + ecol;
            int Cp = mt*16 + erow;
            float* op = out + ((((size_t)b*NC + Cp)*IMG + (size_t)p*WSZ + Hp)*IMG
                               + (size_t)q*WSZ + Wp);
            *(float2*)op = make_float2(acc[mt][g][0], acc[mt][g][1]);
            float* op2 = op + (size_t)8*IMG*IMG;   // Cp+8
            *(float2*)op2 = make_float2(acc[mt][g][2], acc[mt][g][3]);
        }
}

extern "C" void kernel_launch(void* const* d_in, const int* in_sizes, int n_in,
                              void* d_out, int out_size)
{
    const float* x  = (const float*)d_in[0];
    const float* Ws = (const float*)d_in[1];
    const float* Hs = (const float*)d_in[2];
    const float* Cs = (const float*)d_in[3];
    float* out = (float*)d_out;

    cudaFuncSetAttribute(k_stage12, cudaFuncAttributeMaxDynamicSharedMemorySize,
                         SM12_TOTAL);
    cudaFuncSetAttribute(k_stage3, cudaFuncAttributeMaxDynamicSharedMemorySize,
                         SM3_TOTAL);

    k_prep<<<48, 256>>>(Ws, Hs, Cs);

    dim3 gA(64, NC/4, NB);                // 3072 CTAs, 256 threads
    k_stage12<<<gA, 256, SM12_TOTAL>>>(x);

    dim3 gB(16, NWIN);                    // 4096 CTAs, 256 threads
    k_stage3<<<gB, 256, SM3_TOTAL>>>(out);
}

// round 13
// speedup vs baseline: 6.8207x; 1.0420x over previous
#include <cuda_runtime.h>
#include <cuda_fp16.h>
#include <cstdint>

typedef unsigned short ushort_t;

// Problem constants
#define WSZ   64
#define NC    48
#define NT    3
#define NB    4
#define IMG   512
#define KTOT  (NT*NC)            // 144
#define NWIN  (NB*8*8)           // 256

// G scratch, single fp16 plane: [win][k=(t*48+c)][n=H'*64+W']  (288 MiB)
__device__ __align__(16) ushort_t Gf[(size_t)NWIN * KTOT * 4096];

// Pre-transposed factors, single fp16: [t][n][k]
__device__ __align__(16) ushort_t FWs[NT*WSZ*WSZ];
__device__ __align__(16) ushort_t FHs[NT*WSZ*WSZ];
// Cs^T single fp16: [C'][k=t*48+c]
__device__ __align__(16) ushort_t CsTh[NC*KTOT];

// ---------------------------------------------------------------------------
// helpers
// ---------------------------------------------------------------------------
__device__ __forceinline__ uint32_t smem_u32(const void* p) {
    uint32_t a;
    asm("{ .reg .u64 t; cvta.to.shared.u64 t, %1; cvt.u32.u64 %0, t; }"
        : "=r"(a) : "l"(p));
    return a;
}
__device__ __forceinline__ void ldsm4(uint32_t* r, uint32_t addr) {
    asm volatile("ldmatrix.sync.aligned.m8n8.x4.shared.b16 {%0,%1,%2,%3}, [%4];"
                 : "=r"(r[0]), "=r"(r[1]), "=r"(r[2]), "=r"(r[3]) : "r"(addr));
}
__device__ __forceinline__ void ldsm4t(uint32_t* r, uint32_t addr) {
    asm volatile("ldmatrix.sync.aligned.m8n8.x4.trans.shared.b16 {%0,%1,%2,%3}, [%4];"
                 : "=r"(r[0]), "=r"(r[1]), "=r"(r[2]), "=r"(r[3]) : "r"(addr));
}
__device__ __forceinline__ void mma16816h(float* d, const uint32_t* a,
                                          uint32_t b0, uint32_t b1) {
    asm volatile(
        "mma.sync.aligned.m16n8k16.row.col.f32.f16.f16.f32 "
        "{%0,%1,%2,%3},{%4,%5,%6,%7},{%8,%9},{%0,%1,%2,%3};"
        : "+f"(d[0]), "+f"(d[1]), "+f"(d[2]), "+f"(d[3])
        : "r"(a[0]), "r"(a[1]), "r"(a[2]), "r"(a[3]), "r"(b0), "r"(b1));
}
__device__ __forceinline__ void cpa16(uint32_t dst, const void* src) {
    asm volatile("cp.async.ca.shared.global [%0], [%1], 16;"
                 :: "r"(dst), "l"(src) : "memory");
}
#define CPA_COMMIT() asm volatile("cp.async.commit_group;" ::: "memory")

#define RSTRIDE 144   // smem row stride (bytes per 64-fp16 row)

// Warp GEMM: 32(m) x 32(n) x 64(k), single fp16 A/B, fp32 acc.
__device__ __forceinline__ void gemm32x32(
    uint32_t aA, uint32_t aB, int mrow, int nbase, int lane, float acc[2][4][4])
{
    const int rA = lane & 15;
    const int cA = (lane >> 4) * 8;
    const int mB = lane >> 3;
    const int nB = (mB >> 1) * 8 + (lane & 7);
    const int kB = (mB & 1) * 8;
    const uint32_t pA0 = (uint32_t)((mrow + rA) * RSTRIDE + cA * 2);
    const uint32_t pA1 = pA0 + 16 * RSTRIDE;
    const uint32_t pB0 = (uint32_t)((nbase + nB) * RSTRIDE + kB * 2);
    const uint32_t pB1 = pB0 + 16 * RSTRIDE;

    #pragma unroll
    for (int ks = 0; ks < 4; ks++) {
        const uint32_t ko = ks * 32;
        uint32_t a0[4], a1[4], b0[4], b1[4];
        ldsm4(a0, aA + pA0 + ko);
        ldsm4(a1, aA + pA1 + ko);
        ldsm4(b0, aB + pB0 + ko);
        ldsm4(b1, aB + pB1 + ko);

        mma16816h(acc[0][0], a0, b0[0], b0[1]);
        mma16816h(acc[0][1], a0, b0[2], b0[3]);
        mma16816h(acc[0][2], a0, b1[0], b1[1]);
        mma16816h(acc[0][3], a0, b1[2], b1[3]);
        mma16816h(acc[1][0], a1, b0[0], b0[1]);
        mma16816h(acc[1][1], a1, b0[2], b0[3]);
        mma16816h(acc[1][2], a1, b1[0], b1[1]);
        mma16816h(acc[1][3], a1, b1[2], b1[3]);
    }
}

// ---------------------------------------------------------------------------
// Prep (once, tiny)
// ---------------------------------------------------------------------------
__global__ void k_prep(const float* __restrict__ Ws, const float* __restrict__ Hs,
                       const float* __restrict__ Cs)
{
    int u = blockIdx.x * 256 + threadIdx.x;
    if (u < NT*WSZ*WSZ) {
        int t = u >> 12;
        int r = u & 4095;
        int k = r >> 6;
        int n = r & 63;
        __half w = __float2half_rn(Ws[u]);
        __half h = __float2half_rn(Hs[u]);
        FWs[(t << 12) + n*WSZ + k] = *reinterpret_cast<ushort_t*>(&w);
        FHs[(t << 12) + n*WSZ + k] = *reinterpret_cast<ushort_t*>(&h);
    }
    if (u < KTOT*NC) {
        int k  = u / NC;
        int Cp = u % NC;
        __half v = __float2half_rn(Cs[u]);
        CsTh[Cp*KTOT + k] = *reinterpret_cast<ushort_t*>(&v);
    }
}

// stage12 SMEM (bytes): X4 256 rows, T4 256 rows, FW 64 rows, FH 64 rows
#define OX4  0
#define OT4  36864
#define OFW  73728
#define OFH  82944
#define SM12_TOTAL 92160

// ---------------------------------------------------------------------------
// Stage12: CTA = (b, channel-quad, window). 8 warps. Per t:
//   stage Ws_t->FW and Hs_t->FH together (one barrier);
//   GEMM1: D1[W'][(cc,h)]  = Ws_t^T . X4   -> T4
//   GEMM2: D2[H'][(cc,W')] = Hs_t^T . T4   -> Gf
// ---------------------------------------------------------------------------
__global__ void __launch_bounds__(256) k_stage12(const float* __restrict__ x)
{
    extern __shared__ __align__(16) char smem[];
    const uint32_t S = smem_u32(smem);
    const uint32_t XS = S+OX4, TS = S+OT4, FW = S+OFW, FH = S+OFH;

    const int tid  = threadIdx.x;
    const int lane = tid & 31;
    const int wid  = tid >> 5;
    const int mrow  = (wid >> 2) * 32;
    const int ncol0 = (wid & 3) * 64;

    const int win = blockIdx.x, cq = blockIdx.y, b = blockIdx.z;
    const int q = win & 7, p = win >> 3;
    const int c0 = cq * 4;

    // Stage X4 (4 channels) once as fp16: rows r=(cc,h)
    #pragma unroll
    for (int it = 0; it < 16; it++) {
        int u = it*256 + tid;
        int r = u >> 4, w4 = (u & 15) << 2;
        int cc = r >> 6, h = r & 63;
        const float* src = x + (((size_t)(b*NC + c0 + cc)*IMG + p*WSZ + h)*IMG
                                + q*WSZ + w4);
        float4 v = *(const float4*)src;
        __half2 v01 = __floats2half2_rn(v.x, v.y);
        __half2 v23 = __floats2half2_rn(v.z, v.w);
        uint32_t off = (uint32_t)(r*RSTRIDE + w4*2);
        *(uint32_t*)(smem + OX4 + off)     = *(uint32_t*)&v01;
        *(uint32_t*)(smem + OX4 + off + 4) = *(uint32_t*)&v23;
    }

    const size_t winI = (size_t)((b*8 + p)*8 + q);
    const int erow = lane >> 2;
    const int ecol = (lane & 3) * 2;

    for (int t = 0; t < NT; t++) {
        __syncthreads();   // prev t's T4/F reads complete

        {   // Ws_t -> FW, Hs_t -> FH (512 uint4 each / 256 threads)
            const uint4* sw = (const uint4*)(FWs + (t << 12));
            const uint4* sh = (const uint4*)(FHs + (t << 12));
            #pragma unroll
            for (int i = 0; i < 2; i++) {
                int idx = i*256 + tid;
                uint32_t off = (uint32_t)((idx >> 3)*RSTRIDE + (idx & 7)*16);
                *(uint4*)(smem + OFW + off) = sw[idx];
                *(uint4*)(smem + OFH + off) = sh[idx];
            }
        }
        __syncthreads();   // FW/FH ready (and X4 at t=0)

        // GEMM1 (two 32x32 halves) + epilogue1 (write T4; disjoint from X4/FW)
        #pragma unroll
        for (int half = 0; half < 2; half++) {
            const int nbase = ncol0 + half*32;
            float acc[2][4][4];
            #pragma unroll
            for (int a1 = 0; a1 < 2; a1++)
                #pragma unroll
                for (int a2 = 0; a2 < 4; a2++)
                    #pragma unroll
                    for (int a3 = 0; a3 < 4; a3++) acc[a1][a2][a3] = 0.0f;
            gemm32x32(FW, XS, mrow, nbase, lane, acc);

            const int cc = nbase >> 6;
            const int hb = nbase & 63;
            #pragma unroll
            for (int mt = 0; mt < 2; mt++)
                #pragma unroll
                for (int g = 0; g < 4; g++) {
                    int m = mrow + mt*16 + erow;       // W'
                    int h = hb + g*8 + ecol;
                    __half2 v01 = __floats2half2_rn(acc[mt][g][0], acc[mt][g][1]);
                    __half2 v23 = __floats2half2_rn(acc[mt][g][2], acc[mt][g][3]);
                    uint32_t o = (uint32_t)((cc*64 + m)*RSTRIDE + h*2);
                    *(uint32_t*)(smem + OT4 + o)             = *(uint32_t*)&v01;
                    *(uint32_t*)(smem + OT4 + o + 8*RSTRIDE) = *(uint32_t*)&v23;
                }
        }
        __syncthreads();   // T4 complete

        // GEMM2 + epilogue2 (global store; no barrier needed after)
        #pragma unroll
        for (int half = 0; half < 2; half++) {
            const int nbase = ncol0 + half*32;
            float acc[2][4][4];
            #pragma unroll
            for (int a1 = 0; a1 < 2; a1++)
                #pragma unroll
                for (int a2 = 0; a2 < 4; a2++)
                    #pragma unroll
                    for (int a3 = 0; a3 < 4; a3++) acc[a1][a2][a3] = 0.0f;
            gemm32x32(FH, TS, mrow, nbase, lane, acc);

            const int cc = nbase >> 6;
            const int wb = nbase & 63;
            ushort_t* gf = Gf + (winI*KTOT + (size_t)(t*NC + c0 + cc)) * 4096;
            #pragma unroll
            for (int mt = 0; mt < 2; mt++)
                #pragma unroll
                for (int g = 0; g < 4; g++) {
                    int m = mrow + mt*16 + erow;       // H'
                    int Wp = wb + g*8 + ecol;
                    __half2 v01 = __floats2half2_rn(acc[mt][g][0], acc[mt][g][1]);
                    __half2 v23 = __floats2half2_rn(acc[mt][g][2], acc[mt][g][3]);
                    *(uint32_t*)&gf[m*WSZ + Wp]     = *(uint32_t*)&v01;
                    *(uint32_t*)&gf[(m+8)*WSZ + Wp] = *(uint32_t*)&v23;
                }
        }
    }
}

// ---------------------------------------------------------------------------
// Stage3: per (window, 256-n tile): out[48][256] = CsT[48][144] . G[144][256]
// 4-buffer cp.async pipeline, 3 chunks in flight.
// ---------------------------------------------------------------------------
#define ASTR3 336
#define BSTR 528
#define BBUF 8448
#define OA3 0
#define OB3 16128
#define SM3_TOTAL (OB3 + 4*BBUF)   // 49920

__global__ void __launch_bounds__(256) k_stage3(float* __restrict__ out)
{
    extern __shared__ __align__(16) char smem[];
    const uint32_t S = smem_u32(smem);
    const uint32_t AH = S+OA3, B0 = S+OB3;

    const int tid  = threadIdx.x;
    const int lane = tid & 31;
    const int wid  = tid >> 5;
    const int win   = blockIdx.y;
    const int ntile = blockIdx.x;
    const int nloc = (wid >> 1) * 64 + (wid & 1) * 32;

    for (int i = tid; i < 864; i += 256) {
        int r = i / 18, u = i % 18;
        *(uint4*)(smem + OA3 + (uint32_t)(r*ASTR3 + u*16)) =
            *(const uint4*)(CsTh + r*KTOT + u*8);
    }

    const size_t gbase = (size_t)win * KTOT * 4096 + (size_t)ntile * 256;
    const ushort_t* gf = Gf + gbase;

    const int k0a = tid >> 5,         lua = tid & 31;
    const int k0b = (tid + 256) >> 5, lub = tid & 31;

    // Prologue: issue chunks 0,1,2
    #pragma unroll
    for (int j = 0; j < 3; j++) {
        uint32_t Bd = B0 + (uint32_t)(j * BBUF);
        cpa16(Bd + (uint32_t)(k0a*BSTR + lua*16), gf + (size_t)(j*16 + k0a)*4096 + lua*8);
        cpa16(Bd + (uint32_t)(k0b*BSTR + lub*16), gf + (size_t)(j*16 + k0b)*4096 + lub*8);
        CPA_COMMIT();
    }
    __syncthreads();   // A visible

    const int rA = lane & 15;
    const int cA = (lane >> 4) * 8;
    const int rB = (lane & 7) + ((lane >> 3) & 1) * 8;
    const int cB = ((lane >> 4) & 1) * 8;

    float acc[3][4][4];
    #pragma unroll
    for (int i = 0; i < 3; i++)
        #pragma unroll
        for (int j = 0; j < 4; j++)
            #pragma unroll
            for (int k = 0; k < 4; k++) acc[i][j][k] = 0.0f;

    for (int kc = 0; kc < 9; kc++) {
        // chunk kc must be complete: allowed outstanding = committed - (kc+1)
        if      (kc <= 6) asm volatile("cp.async.wait_group 2;" ::: "memory");
        else if (kc == 7) asm volatile("cp.async.wait_group 1;" ::: "memory");
        else              asm volatile("cp.async.wait_group 0;" ::: "memory");
        __syncthreads();

        // issue chunk kc+3 into buffer (kc+3)%4 (consumed at kc-1)
        if (kc <= 5) {
            int j = kc + 3;
            uint32_t Bd = B0 + (uint32_t)((j & 3) * BBUF);
            cpa16(Bd + (uint32_t)(k0a*BSTR + lua*16), gf + (size_t)(j*16 + k0a)*4096 + lua*8);
            cpa16(Bd + (uint32_t)(k0b*BSTR + lub*16), gf + (size_t)(j*16 + k0b)*4096 + lub*8);
            CPA_COMMIT();
        }

        uint32_t a[3][4];
        #pragma unroll
        for (int mt = 0; mt < 3; mt++)
            ldsm4(a[mt], AH + (uint32_t)((mt*16 + rA)*ASTR3 + (kc*16 + cA)*2));
        const uint32_t Bc = B0 + (uint32_t)((kc & 3) * BBUF);
        uint32_t bf[2][4];
        #pragma unroll
        for (int ng = 0; ng < 2; ng++)
            ldsm4t(bf[ng], Bc + (uint32_t)(rB*BSTR + (nloc + ng*16 + cB)*2));

        #pragma unroll
        for (int mt = 0; mt < 3; mt++)
            #pragma unroll
            for (int ng = 0; ng < 2; ng++) {
                mma16816h(acc[mt][ng*2  ], a[mt], bf[ng][0], bf[ng][1]);
                mma16816h(acc[mt][ng*2+1], a[mt], bf[ng][2], bf[ng][3]);
            }
    }

    const int b = win >> 6;
    const int p = (win >> 3) & 7;
    const int q = win & 7;
    const int Hp = ntile*4 + (wid >> 1);
    const int erow = lane >> 2;
    const int ecol = (lane & 3) * 2;
    #pragma unroll
    for (int mt = 0; mt < 3; mt++)
        #pragma unroll
        for (int g = 0; g < 4; g++) {
            int Wp = (wid & 1)*32 + g*8 + ecol;
            int Cp = mt*16 + erow;
            float* op = out + ((((size_t)b*NC + Cp)*IMG + (size_t)p*WSZ + Hp)*IMG
                               + (size_t)q*WSZ + Wp);
            *(float2*)op = make_float2(acc[mt][g][0], acc[mt][g][1]);
            float* op2 = op + (size_t)8*IMG*IMG;   // Cp+8
            *(float2*)op2 = make_float2(acc[mt][g][2], acc[mt][g][3]);
        }
}

extern "C" void kernel_launch(void* const* d_in, const int* in_sizes, int n_in,
                              void* d_out, int out_size)
{
    const float* x  = (const float*)d_in[0];
    const float* Ws = (const float*)d_in[1];
    const float* Hs = (const float*)d_in[2];
    const float* Cs = (const float*)d_in[3];
    float* out = (float*)d_out;

    cudaFuncSetAttribute(k_stage12, cudaFuncAttributeMaxDynamicSharedMemorySize,
                         SM12_TOTAL);
    cudaFuncSetAttribute(k_stage3, cudaFuncAttributeMaxDynamicSharedMemorySize,
                         SM3_TOTAL);

    k_prep<<<48, 256>>>(Ws, Hs, Cs);

    dim3 gA(64, NC/4, NB);                // 3072 CTAs
    k_stage12<<<gA, 256, SM12_TOTAL>>>(x);

    dim3 gB(16, NWIN);                    // 4096 CTAs
    k_stage3<<<gB, 256, SM3_TOTAL>>>(out);
}